// round 1
// baseline (speedup 1.0000x reference)
#include <cuda_runtime.h>
#include <math.h>

#define BB 8
#define CC 192
#define HH 128
#define WW 128
#define HWW (HH*WW)          // 16384
#define NHEADS 4
#define SS 48
#define NPB (CC*HWW)         // 3145728 per batch per tensor
#define NTOT (BB*NPB)        // 25165824

// ---------------- scratch (static device memory, no allocs) ----------------
__device__ float g_xn[NTOT];          // layernorm output (residual source)
__device__ float g_tmp[3*NTOT];       // pointwise conv outputs Qp,Kp,Vp; slot2 reused as Vt
__device__ float g_qkv[3*NTOT];       // after depthwise: Q,K,V
__device__ float g_att[BB*NHEADS*SS*SS];
__device__ float g_GT[BB*CC*CC];      // per-batch fused matrix, stored [b][c][o] (K-major for GEMM)
__device__ float g_w3t[CC*3*CC];      // combined pw weights, transposed: [k][m], m = conv*192+o
__device__ float g_b3[3*CC];

// ---------------- weight prep ----------------
__global__ void prep_weights_kernel(const float* __restrict__ qw, const float* __restrict__ kw,
                                    const float* __restrict__ vw, const float* __restrict__ qb,
                                    const float* __restrict__ kb, const float* __restrict__ vb) {
    int idx = blockIdx.x * 256 + threadIdx.x;
    if (idx < CC * 3 * CC) {
        int k = idx / (3 * CC), m = idx % (3 * CC);
        int i = m / CC, o = m % CC;
        const float* w = (i == 0) ? qw : (i == 1) ? kw : vw;
        g_w3t[idx] = w[o * CC + k];
    }
    if (idx < 3 * CC) {
        int i = idx / CC, o = idx % CC;
        const float* bs = (i == 0) ? qb : (i == 1) ? kb : vb;
        g_b3[idx] = bs[o];
    }
}

__global__ void zero_att_kernel() {
    int idx = blockIdx.x * 256 + threadIdx.x;
    if (idx < BB * NHEADS * SS * SS) g_att[idx] = 0.0f;
}

// ---------------- layernorm over channel axis ----------------
__global__ __launch_bounds__(256) void ln_kernel(const float* __restrict__ x,
                                                 const float* __restrict__ lw,
                                                 const float* __restrict__ lb) {
    int p = blockIdx.x * 256 + threadIdx.x;
    if (p >= BB * HWW) return;
    int b = p / HWW, sp = p % HWW;
    const float* xp = x + (size_t)b * NPB + sp;
    float s = 0.f, sq = 0.f;
    #pragma unroll 4
    for (int c = 0; c < CC; c++) {
        float v = xp[(size_t)c * HWW];
        s += v; sq += v * v;
    }
    float mu = s * (1.0f / CC);
    float var = sq * (1.0f / CC) - mu * mu;
    float r = rsqrtf(var + 1e-5f);
    float* op = g_xn + (size_t)b * NPB + sp;
    #pragma unroll 4
    for (int c = 0; c < CC; c++) {
        op[(size_t)c * HWW] = (xp[(size_t)c * HWW] - mu) * r * lw[c] + lb[c];
    }
}

// ---------------- fused QKV pointwise GEMM: [576 x 192] @ [192 x HW] per batch ----------------
__global__ __launch_bounds__(256) void gemm_qkv_kernel() {
    __shared__ float As[64][64];
    __shared__ float Bs[64][64];
    const int tid = threadIdx.x;
    const int tx = tid & 15, ty = tid >> 4;
    const int pix0 = blockIdx.x * 64;
    const int m0 = blockIdx.y * 64;
    const int b = blockIdx.z;
    const float* X = g_xn + (size_t)b * NPB;
    float acc[4][4] = {};
    for (int k0 = 0; k0 < CC; k0 += 64) {
        #pragma unroll
        for (int i = 0; i < 4; i++) {
            int f = tid + i * 256;
            int r = f >> 4, c4 = (f & 15) << 2;
            *(float4*)&As[r][c4] = *(const float4*)&g_w3t[(size_t)(k0 + r) * (3 * CC) + m0 + c4];
            *(float4*)&Bs[r][c4] = *(const float4*)&X[(size_t)(k0 + r) * HWW + pix0 + c4];
        }
        __syncthreads();
        #pragma unroll 8
        for (int kk = 0; kk < 64; kk++) {
            float4 a  = *(float4*)&As[kk][ty << 2];
            float4 bv = *(float4*)&Bs[kk][tx << 2];
            acc[0][0] += a.x * bv.x; acc[0][1] += a.x * bv.y; acc[0][2] += a.x * bv.z; acc[0][3] += a.x * bv.w;
            acc[1][0] += a.y * bv.x; acc[1][1] += a.y * bv.y; acc[1][2] += a.y * bv.z; acc[1][3] += a.y * bv.w;
            acc[2][0] += a.z * bv.x; acc[2][1] += a.z * bv.y; acc[2][2] += a.z * bv.z; acc[2][3] += a.z * bv.w;
            acc[3][0] += a.w * bv.x; acc[3][1] += a.w * bv.y; acc[3][2] += a.w * bv.z; acc[3][3] += a.w * bv.w;
        }
        __syncthreads();
    }
    #pragma unroll
    for (int i = 0; i < 4; i++) {
        int m = m0 + (ty << 2) + i;
        int slot = m / CC, o = m % CC;
        float bias = g_b3[m];
        float4 v = make_float4(acc[i][0] + bias, acc[i][1] + bias, acc[i][2] + bias, acc[i][3] + bias);
        float* Y = g_tmp + ((size_t)slot * BB + b) * NPB + (size_t)o * HWW + pix0 + (tx << 2);
        *(float4*)Y = v;
    }
}

// ---------------- depthwise 3x3 SAME ----------------
__global__ __launch_bounds__(256) void dw_kernel(int slot, const float* __restrict__ wgt,
                                                 const float* __restrict__ bias) {
    int idx = blockIdx.x * 256 + threadIdx.x;
    if (idx >= NTOT) return;
    const float* in = g_tmp + (size_t)slot * NTOT;
    float* out = g_qkv + (size_t)slot * NTOT;
    int w = idx & (WW - 1);
    int h = (idx >> 7) & (HH - 1);
    int cg = idx >> 14;              // b*C + c
    int c = cg % CC;
    const float* ip = in + (size_t)cg * HWW;
    const float* wp = wgt + c * 9;
    float acc = bias[c];
    #pragma unroll
    for (int dy = 0; dy < 3; dy++) {
        int hh = h + dy - 1;
        if (hh < 0 || hh >= HH) continue;
        #pragma unroll
        for (int dx = 0; dx < 3; dx++) {
            int wi = w + dx - 1;
            if (wi < 0 || wi >= WW) continue;
            acc += wp[dy * 3 + dx] * ip[hh * WW + wi];
        }
    }
    out[idx] = acc;
}

// ---------------- spatial transpose of V (torch reshape quirk: H<->W) ----------------
__global__ void transpose_v_kernel() {
    __shared__ float t[32][33];
    int plane = blockIdx.z;                       // b*C + c
    int h0 = blockIdx.y * 32, w0 = blockIdx.x * 32;
    const float* ip = g_qkv + 2 * (size_t)NTOT + (size_t)plane * HWW;
    float* op = g_tmp + 2 * (size_t)NTOT + (size_t)plane * HWW;   // reuse Vp slot as Vt
    int tx = threadIdx.x, ty = threadIdx.y;       // 32 x 8
    #pragma unroll
    for (int i = 0; i < 32; i += 8)
        t[ty + i][tx] = ip[(h0 + ty + i) * WW + w0 + tx];
    __syncthreads();
    #pragma unroll
    for (int i = 0; i < 32; i += 8)
        op[(w0 + ty + i) * WW + h0 + tx] = t[tx][ty + i];
}

// ---------------- per-(b,head) 48x48 Gram: att_raw[s][q] = sum_pix K[s]*Q[q] ----------------
#define GPITCH 129
__global__ __launch_bounds__(256) void gram_kernel() {
    __shared__ float Ks[SS * GPITCH];
    __shared__ float Qs[SS * GPITCH];
    int bh = blockIdx.x;
    int b = bh / NHEADS, hd = bh % NHEADS;
    int p0 = blockIdx.y * 128;
    const float* Qp = g_qkv + (size_t)b * NPB + (size_t)(hd * SS) * HWW + p0;            // slot0 = Q
    const float* Kp = g_qkv + (size_t)NTOT + (size_t)b * NPB + (size_t)(hd * SS) * HWW + p0; // slot1 = K
    int tid = threadIdx.x;
    for (int i = tid; i < SS * 128; i += 256) {
        int s = i >> 7, p = i & 127;
        Ks[s * GPITCH + p] = Kp[(size_t)s * HWW + p];
        Qs[s * GPITCH + p] = Qp[(size_t)s * HWW + p];
    }
    __syncthreads();
    int tx = tid & 15, ty = tid >> 4;
    int s0 = ty * 3, q0 = tx * 3;
    float acc[3][3] = {};
    for (int p = 0; p < 128; p++) {
        float kv0 = Ks[(s0 + 0) * GPITCH + p];
        float kv1 = Ks[(s0 + 1) * GPITCH + p];
        float kv2 = Ks[(s0 + 2) * GPITCH + p];
        float qv0 = Qs[(q0 + 0) * GPITCH + p];
        float qv1 = Qs[(q0 + 1) * GPITCH + p];
        float qv2 = Qs[(q0 + 2) * GPITCH + p];
        acc[0][0] += kv0 * qv0; acc[0][1] += kv0 * qv1; acc[0][2] += kv0 * qv2;
        acc[1][0] += kv1 * qv0; acc[1][1] += kv1 * qv1; acc[1][2] += kv1 * qv2;
        acc[2][0] += kv2 * qv0; acc[2][1] += kv2 * qv1; acc[2][2] += kv2 * qv2;
    }
    float* ap = g_att + (size_t)bh * SS * SS;
    #pragma unroll
    for (int i = 0; i < 3; i++)
        #pragma unroll
        for (int j = 0; j < 3; j++)
            atomicAdd(&ap[(s0 + i) * SS + q0 + j], acc[i][j]);
}

// ---------------- softmax over q (axis -1), rows s ----------------
__global__ void softmax_kernel(const float* __restrict__ alpha) {
    int bh = blockIdx.x;
    int s = threadIdx.x;                // 48 threads
    float inva = 1.0f / alpha[0];
    float* row = g_att + ((size_t)bh * SS + s) * SS;
    float mx = -1e30f;
    for (int q = 0; q < SS; q++) mx = fmaxf(mx, row[q] * inva);
    float sum = 0.f;
    for (int q = 0; q < SS; q++) sum += expf(row[q] * inva - mx);
    float rs = 1.0f / sum;
    for (int q = 0; q < SS; q++) row[q] = expf(row[q] * inva - mx) * rs;
}

// ---------------- build fused per-batch matrix G_T[b][cv][o] = sum_q f_w[o][hd*48+q]*att[b][hd][cv%48][q] ----------------
__global__ void buildG_kernel(const float* __restrict__ fw) {
    int b = blockIdx.x, cv = blockIdx.y;
    int hd = cv / SS, sl = cv % SS;
    __shared__ float arow[SS];
    int o = threadIdx.x;                // 192 threads
    if (o < SS) arow[o] = g_att[(((size_t)b * NHEADS + hd) * SS + sl) * SS + o];
    __syncthreads();
    const float* fp = fw + (size_t)o * CC + hd * SS;
    float acc = 0.f;
    #pragma unroll
    for (int q = 0; q < SS; q++) acc += fp[q] * arow[q];
    g_GT[((size_t)b * CC + cv) * CC + o] = acc;
}

// ---------------- final GEMM: y = G[b] @ Vt + f_b + xn ----------------
__global__ __launch_bounds__(256) void gemm_final_kernel(const float* __restrict__ fb,
                                                         float* __restrict__ out) {
    __shared__ float As[64][64];
    __shared__ float Bs[64][64];
    const int tid = threadIdx.x;
    const int tx = tid & 15, ty = tid >> 4;
    const int pix0 = blockIdx.x * 64;
    const int m0 = blockIdx.y * 64;
    const int b = blockIdx.z;
    const float* At = g_GT + (size_t)b * CC * CC;
    const float* X = g_tmp + 2 * (size_t)NTOT + (size_t)b * NPB;  // Vt
    float acc[4][4] = {};
    for (int k0 = 0; k0 < CC; k0 += 64) {
        #pragma unroll
        for (int i = 0; i < 4; i++) {
            int f = tid + i * 256;
            int r = f >> 4, c4 = (f & 15) << 2;
            *(float4*)&As[r][c4] = *(const float4*)&At[(size_t)(k0 + r) * CC + m0 + c4];
            *(float4*)&Bs[r][c4] = *(const float4*)&X[(size_t)(k0 + r) * HWW + pix0 + c4];
        }
        __syncthreads();
        #pragma unroll 8
        for (int kk = 0; kk < 64; kk++) {
            float4 a  = *(float4*)&As[kk][ty << 2];
            float4 bv = *(float4*)&Bs[kk][tx << 2];
            acc[0][0] += a.x * bv.x; acc[0][1] += a.x * bv.y; acc[0][2] += a.x * bv.z; acc[0][3] += a.x * bv.w;
            acc[1][0] += a.y * bv.x; acc[1][1] += a.y * bv.y; acc[1][2] += a.y * bv.z; acc[1][3] += a.y * bv.w;
            acc[2][0] += a.z * bv.x; acc[2][1] += a.z * bv.y; acc[2][2] += a.z * bv.z; acc[2][3] += a.z * bv.w;
            acc[3][0] += a.w * bv.x; acc[3][1] += a.w * bv.y; acc[3][2] += a.w * bv.z; acc[3][3] += a.w * bv.w;
        }
        __syncthreads();
    }
    #pragma unroll
    for (int i = 0; i < 4; i++) {
        int m = m0 + (ty << 2) + i;
        float bias = fb[m];
        size_t base = ((size_t)b * CC + m) * HWW + pix0 + (tx << 2);
        float4 xv = *(const float4*)&g_xn[base];
        float4 v = make_float4(acc[i][0] + bias + xv.x, acc[i][1] + bias + xv.y,
                               acc[i][2] + bias + xv.z, acc[i][3] + bias + xv.w);
        *(float4*)&out[base] = v;
    }
}

// ---------------- launch ----------------
extern "C" void kernel_launch(void* const* d_in, const int* in_sizes, int n_in,
                              void* d_out, int out_size) {
    const float* x      = (const float*)d_in[0];
    const float* ln_w   = (const float*)d_in[1];
    const float* ln_b   = (const float*)d_in[2];
    const float* q_pw_w = (const float*)d_in[3];
    const float* q_pw_b = (const float*)d_in[4];
    const float* q_dw_w = (const float*)d_in[5];
    const float* q_dw_b = (const float*)d_in[6];
    const float* k_pw_w = (const float*)d_in[7];
    const float* k_pw_b = (const float*)d_in[8];
    const float* k_dw_w = (const float*)d_in[9];
    const float* k_dw_b = (const float*)d_in[10];
    const float* v_pw_w = (const float*)d_in[11];
    const float* v_pw_b = (const float*)d_in[12];
    const float* v_dw_w = (const float*)d_in[13];
    const float* v_dw_b = (const float*)d_in[14];
    const float* f_w    = (const float*)d_in[15];
    const float* f_b    = (const float*)d_in[16];
    const float* alpha  = (const float*)d_in[17];
    float* out = (float*)d_out;

    prep_weights_kernel<<<(CC * 3 * CC + 255) / 256, 256>>>(q_pw_w, k_pw_w, v_pw_w,
                                                            q_pw_b, k_pw_b, v_pw_b);
    zero_att_kernel<<<(BB * NHEADS * SS * SS + 255) / 256, 256>>>();
    ln_kernel<<<(BB * HWW + 255) / 256, 256>>>(x, ln_w, ln_b);
    gemm_qkv_kernel<<<dim3(HWW / 64, (3 * CC) / 64, BB), 256>>>();
    dw_kernel<<<(NTOT + 255) / 256, 256>>>(0, q_dw_w, q_dw_b);
    dw_kernel<<<(NTOT + 255) / 256, 256>>>(1, k_dw_w, k_dw_b);
    dw_kernel<<<(NTOT + 255) / 256, 256>>>(2, v_dw_w, v_dw_b);
    transpose_v_kernel<<<dim3(4, 4, BB * CC), dim3(32, 8)>>>();
    gram_kernel<<<dim3(BB * NHEADS, HWW / 128), 256>>>();
    softmax_kernel<<<BB * NHEADS, SS>>>(alpha);
    buildG_kernel<<<dim3(BB, CC), CC>>>(f_w);
    gemm_final_kernel<<<dim3(HWW / 64, CC / 64, BB), 256>>>(f_b, out);
}

// round 5
// speedup vs baseline: 1.0560x; 1.0560x over previous
#include <cuda_runtime.h>
#include <math.h>
#include <stdint.h>

#define BB 8
#define CC 192
#define HH 128
#define WW 128
#define HWW (HH*WW)          // 16384
#define NHEADS 4
#define SS 48
#define NPB (CC*HWW)         // 3145728 per batch per tensor
#define NTOT (BB*NPB)

// ---------------- scratch ----------------
__device__ float g_xn[NTOT];          // layernorm output, channel-planar (residual)
__device__ float g_tmp[3*NTOT];       // pw outputs Qp,Kp,Vp ; slot2 reused as Vt after dw
__device__ float g_qkv[3*NTOT];       // after depthwise: Q,K,V (planar)
__device__ float g_att[BB*NHEADS*SS*SS];
__device__ float g_GT[BB*CC*CC];      // fused matrix per batch, [b][cv][o] (K-major for SIMT GEMM)
__device__ float g_w3[640*CC];        // stacked pw weights [m(pad 640)][k]
__device__ float g_b3[3*CC];

__device__ __forceinline__ uint32_t tf32_rna(float x) {
    uint32_t u;
    asm("cvt.rna.tf32.f32 %0, %1;" : "=r"(u) : "f"(x));
    return u;
}
__device__ __forceinline__ void tf32_split(float x, uint32_t& hi, uint32_t& lo) {
    hi = tf32_rna(x);
    lo = tf32_rna(x - __uint_as_float(hi));
}

// ---------------- weight prep ----------------
__global__ void prep_weights_kernel(const float* __restrict__ qw, const float* __restrict__ kw,
                                    const float* __restrict__ vw, const float* __restrict__ qb,
                                    const float* __restrict__ kb, const float* __restrict__ vb) {
    int idx = blockIdx.x * 256 + threadIdx.x;
    if (idx < 640 * CC) {
        int m = idx / CC, k = idx % CC;
        float v = 0.0f;
        if (m < 576) {
            int slot = m / CC, o = m % CC;
            const float* w = (slot == 0) ? qw : (slot == 1) ? kw : vw;
            v = w[o * CC + k];
        }
        g_w3[idx] = v;
    }
    if (idx < 3 * CC) {
        int i = idx / CC, o = idx % CC;
        const float* bs = (i == 0) ? qb : (i == 1) ? kb : vb;
        g_b3[idx] = bs[o];
    }
}

__global__ void zero_att_kernel() {
    int idx = blockIdx.x * 256 + threadIdx.x;
    if (idx < BB * NHEADS * SS * SS) g_att[idx] = 0.0f;
}

// ---------------- layernorm over channel axis (planar out) ----------------
__global__ __launch_bounds__(256) void ln_kernel(const float* __restrict__ x,
                                                 const float* __restrict__ lw,
                                                 const float* __restrict__ lb) {
    int p = blockIdx.x * 256 + threadIdx.x;
    if (p >= BB * HWW) return;
    int b = p / HWW, sp = p % HWW;
    const float* xp = x + (size_t)b * NPB + sp;
    float s = 0.f, sq = 0.f;
    #pragma unroll 4
    for (int c = 0; c < CC; c++) {
        float v = xp[(size_t)c * HWW];
        s += v; sq += v * v;
    }
    float mu = s * (1.0f / CC);
    float var = sq * (1.0f / CC) - mu * mu;
    float r = rsqrtf(var + 1e-5f);
    float* op = g_xn + (size_t)b * NPB + sp;
    #pragma unroll 4
    for (int c = 0; c < CC; c++) {
        op[(size_t)c * HWW] = (xp[(size_t)c * HWW] - mu) * r * lw[c] + lb[c];
    }
}

// ============== tf32 mma.sync QKV GEMM: D[128m x 128pix] = W[m][k]*XN[k][pix], K=192 ==============
// Fragment-order smem layouts (conflict-free mainloop loads), raw fp32 stored:
//   Afrag: [msub(8)][ks(8)] blocks of (32 lanes x 4 floats), block stride 132 floats
//   Bfrag: [nsub(16)][ks(8)] blocks of (32 lanes x 2 floats), block stride 66 floats
#define A_STRIDE 132
#define B_STRIDE 66
#define AFRAG_FLOATS (64 * A_STRIDE)    // 8448
#define BFRAG_FLOATS (128 * B_STRIDE)   // 8448
#define GEMM_SMEM ((AFRAG_FLOATS + BFRAG_FLOATS) * 4)

#define MMA_TF32(acc, ah0, ah1, ah2, ah3, bh0, bh1) \
    asm volatile( \
        "mma.sync.aligned.m16n8k8.row.col.f32.tf32.tf32.f32 " \
        "{%0,%1,%2,%3}, {%4,%5,%6,%7}, {%8,%9}, {%0,%1,%2,%3};" \
        : "+f"((acc)[0]), "+f"((acc)[1]), "+f"((acc)[2]), "+f"((acc)[3]) \
        : "r"(ah0), "r"(ah1), "r"(ah2), "r"(ah3), "r"(bh0), "r"(bh1))

__global__ __launch_bounds__(256) void gemm_qkv_mma_kernel() {
    extern __shared__ float sm[];
    float* Af = sm;
    float* Bf = sm + AFRAG_FLOATS;
    const int tid = threadIdx.x;
    const int wid = tid >> 5, lane = tid & 31;
    const int m0 = blockIdx.y * 128;
    const int b = blockIdx.z;
    const int pix0 = blockIdx.x * 128;

    const float* Amat = g_w3 + (size_t)m0 * CC;
    const float* X = g_xn + (size_t)b * NPB;      // planar [k][pix]

    const int wm = (wid & 1) * 4;    // msub base
    const int wn = (wid >> 1) * 4;   // nsub base

    float acc[4][4][4] = {};

    for (int kc = 0; kc < 3; kc++) {
        if (kc) __syncthreads();
        // ---- fill A fragments (raw fp32, float4 from weight matrix) ----
        #pragma unroll
        for (int f = tid; f < 2048; f += 256) {
            int r = f >> 4;
            int k4 = (f & 15) << 2;
            float4 v = *(const float4*)&Amat[(size_t)r * CC + kc * 64 + k4];
            int ks = k4 >> 3, hik = (k4 >> 2) & 1;
            int msub = r >> 4, rr = r & 15, g = rr & 7, hir = rr >> 3;
            float* base = Af + ((msub * 8 + ks) * A_STRIDE + g * 16 + hir + 2 * hik);
            base[0] = v.x; base[4] = v.y; base[8] = v.z; base[12] = v.w;
        }
        // ---- fill B fragments from PLANAR xn: coalesced scalar (n fastest) ----
        #pragma unroll
        for (int f = tid; f < 8192; f += 256) {
            int n = f & 127;
            int kk = f >> 7;           // 0..63
            float v = X[(size_t)(kc * 64 + kk) * HWW + pix0 + n];
            int nsub = n >> 3, g = n & 7;
            int ks = kk >> 3, kr = kk & 7;
            int hik = kr >> 2, j = kr & 3;
            Bf[(nsub * 8 + ks) * B_STRIDE + g * 8 + j * 2 + hik] = v;
        }
        __syncthreads();
        // ---- mainloop: 8 K-steps of 8, 3xTF32 ----
        #pragma unroll
        for (int ks = 0; ks < 8; ks++) {
            uint32_t ah[4][4], al[4][4], bh[4][2], bl[4][2];
            #pragma unroll
            for (int i = 0; i < 4; i++) {
                float4 t = *(float4*)(Af + ((wm + i) * 8 + ks) * A_STRIDE + lane * 4);
                tf32_split(t.x, ah[i][0], al[i][0]);
                tf32_split(t.y, ah[i][1], al[i][1]);
                tf32_split(t.z, ah[i][2], al[i][2]);
                tf32_split(t.w, ah[i][3], al[i][3]);
            }
            #pragma unroll
            for (int j = 0; j < 4; j++) {
                float2 t = *(float2*)(Bf + ((wn + j) * 8 + ks) * B_STRIDE + lane * 2);
                tf32_split(t.x, bh[j][0], bl[j][0]);
                tf32_split(t.y, bh[j][1], bl[j][1]);
            }
            #pragma unroll
            for (int i = 0; i < 4; i++)
                #pragma unroll
                for (int j = 0; j < 4; j++) {
                    MMA_TF32(acc[i][j], ah[i][0], ah[i][1], ah[i][2], ah[i][3], bl[j][0], bl[j][1]);
                    MMA_TF32(acc[i][j], al[i][0], al[i][1], al[i][2], al[i][3], bh[j][0], bh[j][1]);
                    MMA_TF32(acc[i][j], ah[i][0], ah[i][1], ah[i][2], ah[i][3], bh[j][0], bh[j][1]);
                }
        }
    }

    // ---- epilogue: planar stores + bias ----
    int g = lane >> 2, t = lane & 3;
    #pragma unroll
    for (int i = 0; i < 4; i++) {
        #pragma unroll
        for (int half = 0; half < 2; half++) {
            int m = m0 + (wid & 1) * 64 + i * 16 + g + half * 8;
            if (m >= 576) continue;
            int slot = m / CC, o = m - slot * CC;
            float bias = g_b3[m];
            float* dst = g_tmp + (size_t)slot * NTOT + (size_t)b * NPB + (size_t)o * HWW;
            #pragma unroll
            for (int j = 0; j < 4; j++) {
                int pix = pix0 + (wid >> 1) * 32 + j * 8 + 2 * t;
                float2 v = make_float2(acc[i][j][half*2+0] + bias, acc[i][j][half*2+1] + bias);
                *(float2*)&dst[pix] = v;
            }
        }
    }
}

// ---------------- depthwise 3x3 SAME ----------------
__global__ __launch_bounds__(256) void dw_kernel(int slot, const float* __restrict__ wgt,
                                                 const float* __restrict__ bias) {
    int idx = blockIdx.x * 256 + threadIdx.x;
    if (idx >= NTOT) return;
    const float* in = g_tmp + (size_t)slot * NTOT;
    float* out = g_qkv + (size_t)slot * NTOT;
    int w = idx & (WW - 1);
    int h = (idx >> 7) & (HH - 1);
    int cg = idx >> 14;              // b*C + c
    int c = cg % CC;
    const float* ip = in + (size_t)cg * HWW;
    const float* wp = wgt + c * 9;
    float acc = bias[c];
    #pragma unroll
    for (int dy = 0; dy < 3; dy++) {
        int hh = h + dy - 1;
        if (hh < 0 || hh >= HH) continue;
        #pragma unroll
        for (int dx = 0; dx < 3; dx++) {
            int wi = w + dx - 1;
            if (wi < 0 || wi >= WW) continue;
            acc += wp[dy * 3 + dx] * ip[hh * WW + wi];
        }
    }
    out[idx] = acc;
}

// ---------------- spatial transpose of V (torch reshape quirk: H<->W) ----------------
__global__ void transpose_v_kernel() {
    __shared__ float t[32][33];
    int plane = blockIdx.z;                       // b*C + c
    int h0 = blockIdx.y * 32, w0 = blockIdx.x * 32;
    const float* ip = g_qkv + 2 * (size_t)NTOT + (size_t)plane * HWW;
    float* op = g_tmp + 2 * (size_t)NTOT + (size_t)plane * HWW;   // reuse Vp slot as Vt
    int tx = threadIdx.x, ty = threadIdx.y;       // 32 x 8
    #pragma unroll
    for (int i = 0; i < 32; i += 8)
        t[ty + i][tx] = ip[(h0 + ty + i) * WW + w0 + tx];
    __syncthreads();
    #pragma unroll
    for (int i = 0; i < 32; i += 8)
        op[(w0 + ty + i) * WW + h0 + tx] = t[tx][ty + i];
}

// ---------------- per-(b,head) 48x48 Gram: att_raw[s][q] = sum_pix K[s]*Q[q] ----------------
#define GPITCH 129
__global__ __launch_bounds__(256) void gram_kernel() {
    __shared__ float Ks[SS * GPITCH];
    __shared__ float Qs[SS * GPITCH];
    int bh = blockIdx.x;
    int b = bh / NHEADS, hd = bh % NHEADS;
    int p0 = blockIdx.y * 128;
    const float* Qp = g_qkv + (size_t)b * NPB + (size_t)(hd * SS) * HWW + p0;            // slot0 = Q
    const float* Kp = g_qkv + (size_t)NTOT + (size_t)b * NPB + (size_t)(hd * SS) * HWW + p0; // slot1 = K
    int tid = threadIdx.x;
    for (int i = tid; i < SS * 128; i += 256) {
        int s = i >> 7, p = i & 127;
        Ks[s * GPITCH + p] = Kp[(size_t)s * HWW + p];
        Qs[s * GPITCH + p] = Qp[(size_t)s * HWW + p];
    }
    __syncthreads();
    int tx = tid & 15, ty = tid >> 4;
    int s0 = ty * 3, q0 = tx * 3;
    float acc[3][3] = {};
    for (int p = 0; p < 128; p++) {
        float kv0 = Ks[(s0 + 0) * GPITCH + p];
        float kv1 = Ks[(s0 + 1) * GPITCH + p];
        float kv2 = Ks[(s0 + 2) * GPITCH + p];
        float qv0 = Qs[(q0 + 0) * GPITCH + p];
        float qv1 = Qs[(q0 + 1) * GPITCH + p];
        float qv2 = Qs[(q0 + 2) * GPITCH + p];
        acc[0][0] += kv0 * qv0; acc[0][1] += kv0 * qv1; acc[0][2] += kv0 * qv2;
        acc[1][0] += kv1 * qv0; acc[1][1] += kv1 * qv1; acc[1][2] += kv1 * qv2;
        acc[2][0] += kv2 * qv0; acc[2][1] += kv2 * qv1; acc[2][2] += kv2 * qv2;
    }
    float* ap = g_att + (size_t)bh * SS * SS;
    #pragma unroll
    for (int i = 0; i < 3; i++)
        #pragma unroll
        for (int j = 0; j < 3; j++)
            atomicAdd(&ap[(s0 + i) * SS + q0 + j], acc[i][j]);
}

// ---------------- softmax over q (axis -1), rows s ----------------
__global__ void softmax_kernel(const float* __restrict__ alpha) {
    int bh = blockIdx.x;
    int s = threadIdx.x;                // 48 threads
    float inva = 1.0f / alpha[0];
    float* row = g_att + ((size_t)bh * SS + s) * SS;
    float mx = -1e30f;
    for (int q = 0; q < SS; q++) mx = fmaxf(mx, row[q] * inva);
    float sum = 0.f;
    for (int q = 0; q < SS; q++) sum += expf(row[q] * inva - mx);
    float rs = 1.0f / sum;
    for (int q = 0; q < SS; q++) row[q] = expf(row[q] * inva - mx) * rs;
}

// ---------------- build fused per-batch matrix G_T[b][cv][o] ----------------
__global__ void buildG_kernel(const float* __restrict__ fw) {
    int b = blockIdx.x, cv = blockIdx.y;
    int hd = cv / SS, sl = cv % SS;
    __shared__ float arow[SS];
    int o = threadIdx.x;                // 192 threads
    if (o < SS) arow[o] = g_att[(((size_t)b * NHEADS + hd) * SS + sl) * SS + o];
    __syncthreads();
    const float* fp = fw + (size_t)o * CC + hd * SS;
    float acc = 0.f;
    #pragma unroll
    for (int q = 0; q < SS; q++) acc += fp[q] * arow[q];
    g_GT[((size_t)b * CC + cv) * CC + o] = acc;
}

// ---------------- final GEMM (SIMT, proven): y = G[b] @ Vt + f_b + xn ----------------
__global__ __launch_bounds__(256) void gemm_final_kernel(const float* __restrict__ fb,
                                                         float* __restrict__ out) {
    __shared__ float As[64][64];
    __shared__ float Bs[64][64];
    const int tid = threadIdx.x;
    const int tx = tid & 15, ty = tid >> 4;
    const int pix0 = blockIdx.x * 64;
    const int m0 = blockIdx.y * 64;
    const int b = blockIdx.z;
    const float* At = g_GT + (size_t)b * CC * CC;
    const float* X = g_tmp + 2 * (size_t)NTOT + (size_t)b * NPB;  // Vt
    float acc[4][4] = {};
    for (int k0 = 0; k0 < CC; k0 += 64) {
        #pragma unroll
        for (int i = 0; i < 4; i++) {
            int f = tid + i * 256;
            int r = f >> 4, c4 = (f & 15) << 2;
            *(float4*)&As[r][c4] = *(const float4*)&At[(size_t)(k0 + r) * CC + m0 + c4];
            *(float4*)&Bs[r][c4] = *(const float4*)&X[(size_t)(k0 + r) * HWW + pix0 + c4];
        }
        __syncthreads();
        #pragma unroll 8
        for (int kk = 0; kk < 64; kk++) {
            float4 a  = *(float4*)&As[kk][ty << 2];
            float4 bv = *(float4*)&Bs[kk][tx << 2];
            acc[0][0] += a.x * bv.x; acc[0][1] += a.x * bv.y; acc[0][2] += a.x * bv.z; acc[0][3] += a.x * bv.w;
            acc[1][0] += a.y * bv.x; acc[1][1] += a.y * bv.y; acc[1][2] += a.y * bv.z; acc[1][3] += a.y * bv.w;
            acc[2][0] += a.z * bv.x; acc[2][1] += a.z * bv.y; acc[2][2] += a.z * bv.z; acc[2][3] += a.z * bv.w;
            acc[3][0] += a.w * bv.x; acc[3][1] += a.w * bv.y; acc[3][2] += a.w * bv.z; acc[3][3] += a.w * bv.w;
        }
        __syncthreads();
    }
    #pragma unroll
    for (int i = 0; i < 4; i++) {
        int m = m0 + (ty << 2) + i;
        float bias = fb[m];
        size_t base = ((size_t)b * CC + m) * HWW + pix0 + (tx << 2);
        float4 xv = *(const float4*)&g_xn[base];
        float4 v = make_float4(acc[i][0] + bias + xv.x, acc[i][1] + bias + xv.y,
                               acc[i][2] + bias + xv.z, acc[i][3] + bias + xv.w);
        *(float4*)&out[base] = v;
    }
}

// ---------------- launch ----------------
extern "C" void kernel_launch(void* const* d_in, const int* in_sizes, int n_in,
                              void* d_out, int out_size) {
    const float* x      = (const float*)d_in[0];
    const float* ln_w   = (const float*)d_in[1];
    const float* ln_b   = (const float*)d_in[2];
    const float* q_pw_w = (const float*)d_in[3];
    const float* q_pw_b = (const float*)d_in[4];
    const float* q_dw_w = (const float*)d_in[5];
    const float* q_dw_b = (const float*)d_in[6];
    const float* k_pw_w = (const float*)d_in[7];
    const float* k_pw_b = (const float*)d_in[8];
    const float* k_dw_w = (const float*)d_in[9];
    const float* k_dw_b = (const float*)d_in[10];
    const float* v_pw_w = (const float*)d_in[11];
    const float* v_pw_b = (const float*)d_in[12];
    const float* v_dw_w = (const float*)d_in[13];
    const float* v_dw_b = (const float*)d_in[14];
    const float* f_w    = (const float*)d_in[15];
    const float* f_b    = (const float*)d_in[16];
    const float* alpha  = (const float*)d_in[17];
    float* out = (float*)d_out;

    cudaFuncSetAttribute(gemm_qkv_mma_kernel, cudaFuncAttributeMaxDynamicSharedMemorySize, GEMM_SMEM);

    prep_weights_kernel<<<(640 * CC + 255) / 256, 256>>>(q_pw_w, k_pw_w, v_pw_w,
                                                         q_pw_b, k_pw_b, v_pw_b);
    zero_att_kernel<<<(BB * NHEADS * SS * SS + 255) / 256, 256>>>();
    ln_kernel<<<(BB * HWW + 255) / 256, 256>>>(x, ln_w, ln_b);
    gemm_qkv_mma_kernel<<<dim3(HWW / 128, 5, BB), 256, GEMM_SMEM>>>();
    dw_kernel<<<(NTOT + 255) / 256, 256>>>(0, q_dw_w, q_dw_b);
    dw_kernel<<<(NTOT + 255) / 256, 256>>>(1, k_dw_w, k_dw_b);
    dw_kernel<<<(NTOT + 255) / 256, 256>>>(2, v_dw_w, v_dw_b);
    transpose_v_kernel<<<dim3(4, 4, BB * CC), dim3(32, 8)>>>();
    gram_kernel<<<dim3(BB * NHEADS, HWW / 128), 256>>>();
    softmax_kernel<<<BB * NHEADS, SS>>>(alpha);
    buildG_kernel<<<dim3(BB, CC), CC>>>(f_w);
    gemm_final_kernel<<<dim3(HWW / 64, CC / 64, BB), 256>>>(f_b, out);
}

// round 6
// speedup vs baseline: 1.0580x; 1.0018x over previous
#include <cuda_runtime.h>
#include <math.h>
#include <stdint.h>

#define BB 8
#define CC 192
#define HH 128
#define WW 128
#define HWW (HH*WW)          // 16384
#define NHEADS 4
#define SS 48
#define NPB (CC*HWW)         // 3145728 per batch per tensor
#define NTOT (BB*NPB)

// ---------------- scratch ----------------
__device__ float g_xn[NTOT];          // layernorm output, channel-planar (residual)
__device__ float g_tmp[3*NTOT];       // pw outputs Qp,Kp,Vp ; slot2 reused as Vt after dw
__device__ float g_qkv[3*NTOT];       // after depthwise: Q,K,V (planar)
__device__ float g_att[BB*NHEADS*SS*SS];
__device__ float g_Gm[BB*256*CC];     // fused matrix per batch, [b][o(pad 256)][cv]  (A row-major [m][k])
__device__ float g_w3[640*CC];        // stacked pw weights [m(pad 640)][k]
__device__ float g_b3[3*CC];

__device__ __forceinline__ uint32_t tf32_rna(float x) {
    uint32_t u;
    asm("cvt.rna.tf32.f32 %0, %1;" : "=r"(u) : "f"(x));
    return u;
}
__device__ __forceinline__ void tf32_split(float x, uint32_t& hi, uint32_t& lo) {
    hi = tf32_rna(x);
    lo = tf32_rna(x - __uint_as_float(hi));
}

// ---------------- weight prep ----------------
__global__ void prep_weights_kernel(const float* __restrict__ qw, const float* __restrict__ kw,
                                    const float* __restrict__ vw, const float* __restrict__ qb,
                                    const float* __restrict__ kb, const float* __restrict__ vb) {
    int idx = blockIdx.x * 256 + threadIdx.x;
    if (idx < 640 * CC) {
        int m = idx / CC, k = idx % CC;
        float v = 0.0f;
        if (m < 576) {
            int slot = m / CC, o = m % CC;
            const float* w = (slot == 0) ? qw : (slot == 1) ? kw : vw;
            v = w[o * CC + k];
        }
        g_w3[idx] = v;
    }
    if (idx < 3 * CC) {
        int i = idx / CC, o = idx % CC;
        const float* bs = (i == 0) ? qb : (i == 1) ? kb : vb;
        g_b3[idx] = bs[o];
    }
}

__global__ void zero_att_kernel() {
    int idx = blockIdx.x * 256 + threadIdx.x;
    if (idx < BB * NHEADS * SS * SS) g_att[idx] = 0.0f;
}

// ---------------- layernorm over channel axis (planar out) ----------------
__global__ __launch_bounds__(256) void ln_kernel(const float* __restrict__ x,
                                                 const float* __restrict__ lw,
                                                 const float* __restrict__ lb) {
    int p = blockIdx.x * 256 + threadIdx.x;
    if (p >= BB * HWW) return;
    int b = p / HWW, sp = p % HWW;
    const float* xp = x + (size_t)b * NPB + sp;
    float s = 0.f, sq = 0.f;
    #pragma unroll 4
    for (int c = 0; c < CC; c++) {
        float v = xp[(size_t)c * HWW];
        s += v; sq += v * v;
    }
    float mu = s * (1.0f / CC);
    float var = sq * (1.0f / CC) - mu * mu;
    float r = rsqrtf(var + 1e-5f);
    float* op = g_xn + (size_t)b * NPB + sp;
    #pragma unroll 4
    for (int c = 0; c < CC; c++) {
        op[(size_t)c * HWW] = (xp[(size_t)c * HWW] - mu) * r * lw[c] + lb[c];
    }
}

// ============== tf32 mma.sync GEMM machinery ==============
// K-chunk 32. Fragment-order smem, pre-split hi/lo:
//   A chunk: [msub(8)][ks(4)] blocks of (32 lanes x 4 floats), stride 132
//   B chunk: [nsub(16)][ks(4)] blocks of (32 lanes x 2 floats), stride 66
#define A_STRIDE 132
#define B_STRIDE 66
#define A_CHUNK (32 * A_STRIDE)   // 4224 floats
#define B_CHUNK (64 * B_STRIDE)   // 4224 floats
#define SMEM_3X ((2 * A_CHUNK + 2 * B_CHUNK) * 4)   // 67584 B
#define SMEM_1X ((A_CHUNK + B_CHUNK) * 4)           // 33792 B

#define MMA_TF32(acc, a0, a1, a2, a3, b0, b1) \
    asm volatile( \
        "mma.sync.aligned.m16n8k8.row.col.f32.tf32.tf32.f32 " \
        "{%0,%1,%2,%3}, {%4,%5,%6,%7}, {%8,%9}, {%0,%1,%2,%3};" \
        : "+f"((acc)[0]), "+f"((acc)[1]), "+f"((acc)[2]), "+f"((acc)[3]) \
        : "r"(a0), "r"(a1), "r"(a2), "r"(a3), "r"(b0), "r"(b1))

// A fill: 128 rows x 32 k from Amat[r*CC + kbase + k]; rows >= arows get zeros.
template<bool THREE>
__device__ __forceinline__ void fill_A(uint32_t* Ah, uint32_t* Al, const float* Amat,
                                       int kbase, int arows, int tid) {
    #pragma unroll
    for (int f = tid; f < 1024; f += 256) {
        int r = f >> 3;
        int k4 = (f & 7) << 2;
        float4 v;
        if (r < arows) v = *(const float4*)&Amat[(size_t)r * CC + kbase + k4];
        else           v = make_float4(0.f, 0.f, 0.f, 0.f);
        int ks = k4 >> 3, hik = (k4 >> 2) & 1;
        int msub = r >> 4, rr = r & 15, g = rr & 7, hir = rr >> 3;
        int base = (msub * 4 + ks) * A_STRIDE + g * 16 + hir + 2 * hik;
        if (THREE) {
            uint32_t h, l;
            tf32_split(v.x, h, l); Ah[base + 0]  = h; Al[base + 0]  = l;
            tf32_split(v.y, h, l); Ah[base + 4]  = h; Al[base + 4]  = l;
            tf32_split(v.z, h, l); Ah[base + 8]  = h; Al[base + 8]  = l;
            tf32_split(v.w, h, l); Ah[base + 12] = h; Al[base + 12] = l;
        } else {
            Ah[base + 0]  = tf32_rna(v.x);
            Ah[base + 4]  = tf32_rna(v.y);
            Ah[base + 8]  = tf32_rna(v.z);
            Ah[base + 12] = tf32_rna(v.w);
        }
    }
}

// B fill from planar X[k][pix]: 128 n x 32 k, coalesced (n fastest).
template<bool THREE>
__device__ __forceinline__ void fill_B(uint32_t* Bh, uint32_t* Bl, const float* X,
                                       int kbase, int pix0, int tid) {
    #pragma unroll
    for (int f = tid; f < 4096; f += 256) {
        int n = f & 127;
        int kk = f >> 7;           // 0..31
        float v = X[(size_t)(kbase + kk) * HWW + pix0 + n];
        int nsub = n >> 3, g = n & 7;
        int ks = kk >> 3, kr = kk & 7;
        int hik = kr >> 2, j = kr & 3;
        int base = (nsub * 4 + ks) * B_STRIDE + g * 8 + j * 2 + hik;
        if (THREE) {
            uint32_t h, l;
            tf32_split(v, h, l);
            Bh[base] = h; Bl[base] = l;
        } else {
            Bh[base] = tf32_rna(v);
        }
    }
}

// Core mainloop over one 32-k chunk (4 k-steps).
template<bool THREE>
__device__ __forceinline__ void mma_chunk(float acc[4][4][4], const uint32_t* Ah, const uint32_t* Al,
                                          const uint32_t* Bh, const uint32_t* Bl,
                                          int wm, int wn, int lane) {
    #pragma unroll
    for (int ks = 0; ks < 4; ks++) {
        uint32_t ah[4][4], al[4][4], bh[4][2], bl[4][2];
        #pragma unroll
        for (int i = 0; i < 4; i++) {
            uint4 t = *(const uint4*)(Ah + ((wm + i) * 4 + ks) * A_STRIDE + lane * 4);
            ah[i][0] = t.x; ah[i][1] = t.y; ah[i][2] = t.z; ah[i][3] = t.w;
            if (THREE) {
                uint4 u = *(const uint4*)(Al + ((wm + i) * 4 + ks) * A_STRIDE + lane * 4);
                al[i][0] = u.x; al[i][1] = u.y; al[i][2] = u.z; al[i][3] = u.w;
            }
        }
        #pragma unroll
        for (int j = 0; j < 4; j++) {
            uint2 t = *(const uint2*)(Bh + ((wn + j) * 4 + ks) * B_STRIDE + lane * 2);
            bh[j][0] = t.x; bh[j][1] = t.y;
            if (THREE) {
                uint2 u = *(const uint2*)(Bl + ((wn + j) * 4 + ks) * B_STRIDE + lane * 2);
                bl[j][0] = u.x; bl[j][1] = u.y;
            }
        }
        #pragma unroll
        for (int i = 0; i < 4; i++)
            #pragma unroll
            for (int j = 0; j < 4; j++) {
                if (THREE) {
                    MMA_TF32(acc[i][j], ah[i][0], ah[i][1], ah[i][2], ah[i][3], bl[j][0], bl[j][1]);
                    MMA_TF32(acc[i][j], al[i][0], al[i][1], al[i][2], al[i][3], bh[j][0], bh[j][1]);
                }
                MMA_TF32(acc[i][j], ah[i][0], ah[i][1], ah[i][2], ah[i][3], bh[j][0], bh[j][1]);
            }
    }
}

// ---------------- QKV pointwise GEMM ----------------
template<bool THREE>
__global__ __launch_bounds__(256) void gemm_qkv_mma_kernel(int m_base) {
    extern __shared__ uint32_t usm[];
    uint32_t* Ah = usm;
    uint32_t* Al = THREE ? (usm + A_CHUNK) : usm;
    uint32_t* Bh = THREE ? (usm + 2 * A_CHUNK) : (usm + A_CHUNK);
    uint32_t* Bl = THREE ? (Bh + B_CHUNK) : Bh;

    const int tid = threadIdx.x;
    const int wid = tid >> 5, lane = tid & 31;
    const int m0 = m_base + blockIdx.y * 128;
    const int b = blockIdx.z;
    const int pix0 = blockIdx.x * 128;

    const float* Amat = g_w3 + (size_t)m0 * CC;
    const float* X = g_xn + (size_t)b * NPB;

    const int wm = (wid & 1) * 4;
    const int wn = (wid >> 1) * 4;

    float acc[4][4][4] = {};

    #pragma unroll 1
    for (int kc = 0; kc < 6; kc++) {
        if (kc) __syncthreads();
        fill_A<THREE>(Ah, Al, Amat, kc * 32, 128, tid);
        fill_B<THREE>(Bh, Bl, X, kc * 32, pix0, tid);
        __syncthreads();
        mma_chunk<THREE>(acc, Ah, Al, Bh, Bl, wm, wn, lane);
    }

    // ---- epilogue: planar stores + bias ----
    int g = lane >> 2, t = lane & 3;
    #pragma unroll
    for (int i = 0; i < 4; i++) {
        #pragma unroll
        for (int half = 0; half < 2; half++) {
            int m = m0 + (wid & 1) * 64 + i * 16 + g + half * 8;
            if (m >= 576) continue;
            int slot = m / CC, o = m - slot * CC;
            float bias = g_b3[m];
            float* dst = g_tmp + (size_t)slot * NTOT + (size_t)b * NPB + (size_t)o * HWW;
            #pragma unroll
            for (int j = 0; j < 4; j++) {
                int pix = pix0 + (wid >> 1) * 32 + j * 8 + 2 * t;
                float2 v = make_float2(acc[i][j][half*2+0] + bias, acc[i][j][half*2+1] + bias);
                *(float2*)&dst[pix] = v;
            }
        }
    }
}

// ---------------- final GEMM (mma, 1xTF32): y = G[b] @ Vt + f_b + xn ----------------
__global__ __launch_bounds__(256) void gemm_final_mma_kernel(const float* __restrict__ fb,
                                                             float* __restrict__ out) {
    extern __shared__ uint32_t usm[];
    uint32_t* Ah = usm;
    uint32_t* Bh = usm + A_CHUNK;

    const int tid = threadIdx.x;
    const int wid = tid >> 5, lane = tid & 31;
    const int m0 = blockIdx.y * 128;
    const int b = blockIdx.z;
    const int pix0 = blockIdx.x * 128;

    const float* Amat = g_Gm + ((size_t)b * 256 + m0) * CC;   // [m][k=cv]
    const float* X = g_tmp + 2 * (size_t)NTOT + (size_t)b * NPB;  // Vt planar [cv][pix]
    const int arows = (m0 == 0) ? 128 : (CC - 128);           // valid A rows in this block

    const int wm = (wid & 1) * 4;
    const int wn = (wid >> 1) * 4;

    float acc[4][4][4] = {};

    #pragma unroll 1
    for (int kc = 0; kc < 6; kc++) {
        if (kc) __syncthreads();
        fill_A<false>(Ah, Ah, Amat, kc * 32, arows, tid);
        fill_B<false>(Bh, Bh, X, kc * 32, pix0, tid);
        __syncthreads();
        mma_chunk<false>(acc, Ah, Ah, Bh, Bh, wm, wn, lane);
    }

    int g = lane >> 2, t = lane & 3;
    #pragma unroll
    for (int i = 0; i < 4; i++) {
        #pragma unroll
        for (int half = 0; half < 2; half++) {
            int m = m0 + (wid & 1) * 64 + i * 16 + g + half * 8;
            if (m >= CC) continue;
            float bias = fb[m];
            size_t base = (size_t)b * NPB + (size_t)m * HWW;
            #pragma unroll
            for (int j = 0; j < 4; j++) {
                int pix = pix0 + (wid >> 1) * 32 + j * 8 + 2 * t;
                float2 xv = *(const float2*)&g_xn[base + pix];
                float2 v = make_float2(acc[i][j][half*2+0] + bias + xv.x,
                                       acc[i][j][half*2+1] + bias + xv.y);
                *(float2*)&out[base + pix] = v;
            }
        }
    }
}

// ---------------- depthwise 3x3 SAME ----------------
__global__ __launch_bounds__(256) void dw_kernel(int slot, const float* __restrict__ wgt,
                                                 const float* __restrict__ bias) {
    int idx = blockIdx.x * 256 + threadIdx.x;
    if (idx >= NTOT) return;
    const float* in = g_tmp + (size_t)slot * NTOT;
    float* out = g_qkv + (size_t)slot * NTOT;
    int w = idx & (WW - 1);
    int h = (idx >> 7) & (HH - 1);
    int cg = idx >> 14;              // b*C + c
    int c = cg % CC;
    const float* ip = in + (size_t)cg * HWW;
    const float* wp = wgt + c * 9;
    float acc = bias[c];
    #pragma unroll
    for (int dy = 0; dy < 3; dy++) {
        int hh = h + dy - 1;
        if (hh < 0 || hh >= HH) continue;
        #pragma unroll
        for (int dx = 0; dx < 3; dx++) {
            int wi = w + dx - 1;
            if (wi < 0 || wi >= WW) continue;
            acc += wp[dy * 3 + dx] * ip[hh * WW + wi];
        }
    }
    out[idx] = acc;
}

// ---------------- spatial transpose of V (torch reshape quirk: H<->W) ----------------
__global__ void transpose_v_kernel() {
    __shared__ float t[32][33];
    int plane = blockIdx.z;                       // b*C + c
    int h0 = blockIdx.y * 32, w0 = blockIdx.x * 32;
    const float* ip = g_qkv + 2 * (size_t)NTOT + (size_t)plane * HWW;
    float* op = g_tmp + 2 * (size_t)NTOT + (size_t)plane * HWW;   // reuse Vp slot as Vt
    int tx = threadIdx.x, ty = threadIdx.y;       // 32 x 8
    #pragma unroll
    for (int i = 0; i < 32; i += 8)
        t[ty + i][tx] = ip[(h0 + ty + i) * WW + w0 + tx];
    __syncthreads();
    #pragma unroll
    for (int i = 0; i < 32; i += 8)
        op[(w0 + ty + i) * WW + h0 + tx] = t[tx][ty + i];
}

// ---------------- per-(b,head) 48x48 Gram: att_raw[s][q] = sum_pix K[s]*Q[q] ----------------
#define GPITCH 129
__global__ __launch_bounds__(256) void gram_kernel() {
    __shared__ float Ks[SS * GPITCH];
    __shared__ float Qs[SS * GPITCH];
    int bh = blockIdx.x;
    int b = bh / NHEADS, hd = bh % NHEADS;
    int p0 = blockIdx.y * 128;
    const float* Qp = g_qkv + (size_t)b * NPB + (size_t)(hd * SS) * HWW + p0;
    const float* Kp = g_qkv + (size_t)NTOT + (size_t)b * NPB + (size_t)(hd * SS) * HWW + p0;
    int tid = threadIdx.x;
    for (int i = tid; i < SS * 128; i += 256) {
        int s = i >> 7, p = i & 127;
        Ks[s * GPITCH + p] = Kp[(size_t)s * HWW + p];
        Qs[s * GPITCH + p] = Qp[(size_t)s * HWW + p];
    }
    __syncthreads();
    int tx = tid & 15, ty = tid >> 4;
    int s0 = ty * 3, q0 = tx * 3;
    float acc[3][3] = {};
    for (int p = 0; p < 128; p++) {
        float kv0 = Ks[(s0 + 0) * GPITCH + p];
        float kv1 = Ks[(s0 + 1) * GPITCH + p];
        float kv2 = Ks[(s0 + 2) * GPITCH + p];
        float qv0 = Qs[(q0 + 0) * GPITCH + p];
        float qv1 = Qs[(q0 + 1) * GPITCH + p];
        float qv2 = Qs[(q0 + 2) * GPITCH + p];
        acc[0][0] += kv0 * qv0; acc[0][1] += kv0 * qv1; acc[0][2] += kv0 * qv2;
        acc[1][0] += kv1 * qv0; acc[1][1] += kv1 * qv1; acc[1][2] += kv1 * qv2;
        acc[2][0] += kv2 * qv0; acc[2][1] += kv2 * qv1; acc[2][2] += kv2 * qv2;
    }
    float* ap = g_att + (size_t)bh * SS * SS;
    #pragma unroll
    for (int i = 0; i < 3; i++)
        #pragma unroll
        for (int j = 0; j < 3; j++)
            atomicAdd(&ap[(s0 + i) * SS + q0 + j], acc[i][j]);
}

// ---------------- softmax over q (axis -1), rows s ----------------
__global__ void softmax_kernel(const float* __restrict__ alpha) {
    int bh = blockIdx.x;
    int s = threadIdx.x;                // 48 threads
    float inva = 1.0f / alpha[0];
    float* row = g_att + ((size_t)bh * SS + s) * SS;
    float mx = -1e30f;
    for (int q = 0; q < SS; q++) mx = fmaxf(mx, row[q] * inva);
    float sum = 0.f;
    for (int q = 0; q < SS; q++) sum += expf(row[q] * inva - mx);
    float rs = 1.0f / sum;
    for (int q = 0; q < SS; q++) row[q] = expf(row[q] * inva - mx) * rs;
}

// ---------------- build fused matrix g_Gm[b][o][cv] = sum_q fw[o][hd*48+q]*att[b][hd][cv%48][q] ----------------
__global__ void buildG_kernel(const float* __restrict__ fw) {
    int b = blockIdx.x, cv = blockIdx.y;
    int hd = cv / SS, sl = cv % SS;
    __shared__ float arow[SS];
    int o = threadIdx.x;                // 192 threads
    if (o < SS) arow[o] = g_att[(((size_t)b * NHEADS + hd) * SS + sl) * SS + o];
    __syncthreads();
    const float* fp = fw + (size_t)o * CC + hd * SS;
    float acc = 0.f;
    #pragma unroll
    for (int q = 0; q < SS; q++) acc += fp[q] * arow[q];
    g_Gm[((size_t)b * 256 + o) * CC + cv] = acc;
}

// ---------------- launch ----------------
extern "C" void kernel_launch(void* const* d_in, const int* in_sizes, int n_in,
                              void* d_out, int out_size) {
    const float* x      = (const float*)d_in[0];
    const float* ln_w   = (const float*)d_in[1];
    const float* ln_b   = (const float*)d_in[2];
    const float* q_pw_w = (const float*)d_in[3];
    const float* q_pw_b = (const float*)d_in[4];
    const float* q_dw_w = (const float*)d_in[5];
    const float* q_dw_b = (const float*)d_in[6];
    const float* k_pw_w = (const float*)d_in[7];
    const float* k_pw_b = (const float*)d_in[8];
    const float* k_dw_w = (const float*)d_in[9];
    const float* k_dw_b = (const float*)d_in[10];
    const float* v_pw_w = (const float*)d_in[11];
    const float* v_pw_b = (const float*)d_in[12];
    const float* v_dw_w = (const float*)d_in[13];
    const float* v_dw_b = (const float*)d_in[14];
    const float* f_w    = (const float*)d_in[15];
    const float* f_b    = (const float*)d_in[16];
    const float* alpha  = (const float*)d_in[17];
    float* out = (float*)d_out;

    cudaFuncSetAttribute(gemm_qkv_mma_kernel<true>,  cudaFuncAttributeMaxDynamicSharedMemorySize, SMEM_3X);
    cudaFuncSetAttribute(gemm_qkv_mma_kernel<false>, cudaFuncAttributeMaxDynamicSharedMemorySize, SMEM_1X);
    cudaFuncSetAttribute(gemm_final_mma_kernel,      cudaFuncAttributeMaxDynamicSharedMemorySize, SMEM_1X);

    prep_weights_kernel<<<(640 * CC + 255) / 256, 256>>>(q_pw_w, k_pw_w, v_pw_w,
                                                         q_pw_b, k_pw_b, v_pw_b);
    zero_att_kernel<<<(BB * NHEADS * SS * SS + 255) / 256, 256>>>();
    ln_kernel<<<(BB * HWW + 255) / 256, 256>>>(x, ln_w, ln_b);
    // Q,K blocks (m 0..383): 3xTF32 for softmax accuracy
    gemm_qkv_mma_kernel<true><<<dim3(HWW / 128, 3, BB), 256, SMEM_3X>>>(0);
    // V blocks (m 384..575): 1xTF32 (damped path)
    gemm_qkv_mma_kernel<false><<<dim3(HWW / 128, 2, BB), 256, SMEM_1X>>>(384);
    dw_kernel<<<(NTOT + 255) / 256, 256>>>(0, q_dw_w, q_dw_b);
    dw_kernel<<<(NTOT + 255) / 256, 256>>>(1, k_dw_w, k_dw_b);
    dw_kernel<<<(NTOT + 255) / 256, 256>>>(2, v_dw_w, v_dw_b);
    transpose_v_kernel<<<dim3(4, 4, BB * CC), dim3(32, 8)>>>();
    gram_kernel<<<dim3(BB * NHEADS, HWW / 128), 256>>>();
    softmax_kernel<<<BB * NHEADS, SS>>>(alpha);
    buildG_kernel<<<dim3(BB, CC), CC>>>(f_w);
    gemm_final_mma_kernel<<<dim3(HWW / 128, 2, BB), 256, SMEM_1X>>>(f_b, out);
}

// round 7
// speedup vs baseline: 1.1577x; 1.0943x over previous
#include <cuda_runtime.h>
#include <math.h>
#include <stdint.h>

#define BB 8
#define CC 192
#define HH 128
#define WW 128
#define HWW (HH*WW)          // 16384
#define NHEADS 4
#define SS 48
#define NPB (CC*HWW)         // 3145728 per batch per tensor
#define NTOT (BB*NPB)

// ---------------- scratch ----------------
__device__ float g_xn[NTOT];          // layernorm output, channel-planar (residual)
__device__ float g_tmp[3*NTOT];       // pw outputs Qp,Kp,Vp ; slot2 reused as Vt after dw
__device__ float g_qkv[3*NTOT];       // after depthwise: Q,K,V (planar)
__device__ float g_att[BB*NHEADS*SS*SS];
__device__ float g_Gm[BB*256*CC];     // fused matrix per batch, [b][o(pad 256)][cv]
__device__ float g_w3[640*CC];        // stacked pw weights [m(pad 640)][k]
__device__ float g_b3[3*CC];

__device__ __forceinline__ uint32_t tf32_rna(float x) {
    uint32_t u;
    asm("cvt.rna.tf32.f32 %0, %1;" : "=r"(u) : "f"(x));
    return u;
}
__device__ __forceinline__ void tf32_split(float x, uint32_t& hi, uint32_t& lo) {
    hi = tf32_rna(x);
    lo = tf32_rna(x - __uint_as_float(hi));
}

// ---------------- weight prep ----------------
__global__ void prep_weights_kernel(const float* __restrict__ qw, const float* __restrict__ kw,
                                    const float* __restrict__ vw, const float* __restrict__ qb,
                                    const float* __restrict__ kb, const float* __restrict__ vb) {
    int idx = blockIdx.x * 256 + threadIdx.x;
    if (idx < 640 * CC) {
        int m = idx / CC, k = idx % CC;
        float v = 0.0f;
        if (m < 576) {
            int slot = m / CC, o = m % CC;
            const float* w = (slot == 0) ? qw : (slot == 1) ? kw : vw;
            v = w[o * CC + k];
        }
        g_w3[idx] = v;
    }
    if (idx < 3 * CC) {
        int i = idx / CC, o = idx % CC;
        const float* bs = (i == 0) ? qb : (i == 1) ? kb : vb;
        g_b3[idx] = bs[o];
    }
}

__global__ void zero_att_kernel() {
    int idx = blockIdx.x * 256 + threadIdx.x;
    if (idx < BB * NHEADS * SS * SS) g_att[idx] = 0.0f;
}

// ---------------- layernorm over channel axis (planar out) ----------------
__global__ __launch_bounds__(256) void ln_kernel(const float* __restrict__ x,
                                                 const float* __restrict__ lw,
                                                 const float* __restrict__ lb) {
    int p = blockIdx.x * 256 + threadIdx.x;
    if (p >= BB * HWW) return;
    int b = p / HWW, sp = p % HWW;
    const float* xp = x + (size_t)b * NPB + sp;
    float s = 0.f, sq = 0.f;
    #pragma unroll 4
    for (int c = 0; c < CC; c++) {
        float v = xp[(size_t)c * HWW];
        s += v; sq += v * v;
    }
    float mu = s * (1.0f / CC);
    float var = sq * (1.0f / CC) - mu * mu;
    float r = rsqrtf(var + 1e-5f);
    float* op = g_xn + (size_t)b * NPB + sp;
    #pragma unroll 4
    for (int c = 0; c < CC; c++) {
        op[(size_t)c * HWW] = (xp[(size_t)c * HWW] - mu) * r * lw[c] + lb[c];
    }
}

// ============== tf32 mma.sync GEMM machinery ==============
#define A_STRIDE 132
#define B_STRIDE 66
#define A_CHUNK (32 * A_STRIDE)   // 4224 floats
#define B_CHUNK (64 * B_STRIDE)   // 4224 floats
#define SMEM_3X ((2 * A_CHUNK + 2 * B_CHUNK) * 4)   // 67584 B
#define SMEM_1X ((A_CHUNK + B_CHUNK) * 4)           // 33792 B

#define MMA_TF32(acc, a0, a1, a2, a3, b0, b1) \
    asm volatile( \
        "mma.sync.aligned.m16n8k8.row.col.f32.tf32.tf32.f32 " \
        "{%0,%1,%2,%3}, {%4,%5,%6,%7}, {%8,%9}, {%0,%1,%2,%3};" \
        : "+f"((acc)[0]), "+f"((acc)[1]), "+f"((acc)[2]), "+f"((acc)[3]) \
        : "r"(a0), "r"(a1), "r"(a2), "r"(a3), "r"(b0), "r"(b1))

template<bool THREE>
__device__ __forceinline__ void fill_A(uint32_t* Ah, uint32_t* Al, const float* Amat,
                                       int kbase, int arows, int tid) {
    #pragma unroll
    for (int f = tid; f < 1024; f += 256) {
        int r = f >> 3;
        int k4 = (f & 7) << 2;
        float4 v;
        if (r < arows) v = *(const float4*)&Amat[(size_t)r * CC + kbase + k4];
        else           v = make_float4(0.f, 0.f, 0.f, 0.f);
        int ks = k4 >> 3, hik = (k4 >> 2) & 1;
        int msub = r >> 4, rr = r & 15, g = rr & 7, hir = rr >> 3;
        int base = (msub * 4 + ks) * A_STRIDE + g * 16 + hir + 2 * hik;
        if (THREE) {
            uint32_t h, l;
            tf32_split(v.x, h, l); Ah[base + 0]  = h; Al[base + 0]  = l;
            tf32_split(v.y, h, l); Ah[base + 4]  = h; Al[base + 4]  = l;
            tf32_split(v.z, h, l); Ah[base + 8]  = h; Al[base + 8]  = l;
            tf32_split(v.w, h, l); Ah[base + 12] = h; Al[base + 12] = l;
        } else {
            Ah[base + 0]  = tf32_rna(v.x);
            Ah[base + 4]  = tf32_rna(v.y);
            Ah[base + 8]  = tf32_rna(v.z);
            Ah[base + 12] = tf32_rna(v.w);
        }
    }
}

template<bool THREE>
__device__ __forceinline__ void fill_B(uint32_t* Bh, uint32_t* Bl, const float* X,
                                       int kbase, int pix0, int tid) {
    #pragma unroll
    for (int f = tid; f < 4096; f += 256) {
        int n = f & 127;
        int kk = f >> 7;           // 0..31
        float v = X[(size_t)(kbase + kk) * HWW + pix0 + n];
        int nsub = n >> 3, g = n & 7;
        int ks = kk >> 3, kr = kk & 7;
        int hik = kr >> 2, j = kr & 3;
        int base = (nsub * 4 + ks) * B_STRIDE + g * 8 + j * 2 + hik;
        if (THREE) {
            uint32_t h, l;
            tf32_split(v, h, l);
            Bh[base] = h; Bl[base] = l;
        } else {
            Bh[base] = tf32_rna(v);
        }
    }
}

template<bool THREE>
__device__ __forceinline__ void mma_chunk(float acc[4][4][4], const uint32_t* Ah, const uint32_t* Al,
                                          const uint32_t* Bh, const uint32_t* Bl,
                                          int wm, int wn, int lane) {
    #pragma unroll
    for (int ks = 0; ks < 4; ks++) {
        uint32_t ah[4][4], al[4][4], bh[4][2], bl[4][2];
        #pragma unroll
        for (int i = 0; i < 4; i++) {
            uint4 t = *(const uint4*)(Ah + ((wm + i) * 4 + ks) * A_STRIDE + lane * 4);
            ah[i][0] = t.x; ah[i][1] = t.y; ah[i][2] = t.z; ah[i][3] = t.w;
            if (THREE) {
                uint4 u = *(const uint4*)(Al + ((wm + i) * 4 + ks) * A_STRIDE + lane * 4);
                al[i][0] = u.x; al[i][1] = u.y; al[i][2] = u.z; al[i][3] = u.w;
            }
        }
        #pragma unroll
        for (int j = 0; j < 4; j++) {
            uint2 t = *(const uint2*)(Bh + ((wn + j) * 4 + ks) * B_STRIDE + lane * 2);
            bh[j][0] = t.x; bh[j][1] = t.y;
            if (THREE) {
                uint2 u = *(const uint2*)(Bl + ((wn + j) * 4 + ks) * B_STRIDE + lane * 2);
                bl[j][0] = u.x; bl[j][1] = u.y;
            }
        }
        #pragma unroll
        for (int i = 0; i < 4; i++)
            #pragma unroll
            for (int j = 0; j < 4; j++) {
                if (THREE) {
                    MMA_TF32(acc[i][j], ah[i][0], ah[i][1], ah[i][2], ah[i][3], bl[j][0], bl[j][1]);
                    MMA_TF32(acc[i][j], al[i][0], al[i][1], al[i][2], al[i][3], bh[j][0], bh[j][1]);
                }
                MMA_TF32(acc[i][j], ah[i][0], ah[i][1], ah[i][2], ah[i][3], bh[j][0], bh[j][1]);
            }
    }
}

// ---------------- QKV pointwise GEMM ----------------
template<bool THREE>
__global__ __launch_bounds__(256, 2) void gemm_qkv_mma_kernel(int m_base) {
    extern __shared__ uint32_t usm[];
    uint32_t* Ah = usm;
    uint32_t* Al = THREE ? (usm + A_CHUNK) : usm;
    uint32_t* Bh = THREE ? (usm + 2 * A_CHUNK) : (usm + A_CHUNK);
    uint32_t* Bl = THREE ? (Bh + B_CHUNK) : Bh;

    const int tid = threadIdx.x;
    const int wid = tid >> 5, lane = tid & 31;
    const int m0 = m_base + blockIdx.y * 128;
    const int b = blockIdx.z;
    const int pix0 = blockIdx.x * 128;

    const float* Amat = g_w3 + (size_t)m0 * CC;
    const float* X = g_xn + (size_t)b * NPB;

    const int wm = (wid & 1) * 4;
    const int wn = (wid >> 1) * 4;

    float acc[4][4][4] = {};

    #pragma unroll 1
    for (int kc = 0; kc < 6; kc++) {
        if (kc) __syncthreads();
        fill_A<THREE>(Ah, Al, Amat, kc * 32, 128, tid);
        fill_B<THREE>(Bh, Bl, X, kc * 32, pix0, tid);
        __syncthreads();
        mma_chunk<THREE>(acc, Ah, Al, Bh, Bl, wm, wn, lane);
    }

    int g = lane >> 2, t = lane & 3;
    #pragma unroll
    for (int i = 0; i < 4; i++) {
        #pragma unroll
        for (int half = 0; half < 2; half++) {
            int m = m0 + (wid & 1) * 64 + i * 16 + g + half * 8;
            if (m >= 576) continue;
            int slot = m / CC, o = m - slot * CC;
            float bias = g_b3[m];
            float* dst = g_tmp + (size_t)slot * NTOT + (size_t)b * NPB + (size_t)o * HWW;
            #pragma unroll
            for (int j = 0; j < 4; j++) {
                int pix = pix0 + (wid >> 1) * 32 + j * 8 + 2 * t;
                float2 v = make_float2(acc[i][j][half*2+0] + bias, acc[i][j][half*2+1] + bias);
                *(float2*)&dst[pix] = v;
            }
        }
    }
}

// ---------------- final GEMM (mma, 1xTF32): y = G[b] @ Vt + f_b + xn ----------------
__global__ __launch_bounds__(256, 2) void gemm_final_mma_kernel(const float* __restrict__ fb,
                                                                float* __restrict__ out) {
    extern __shared__ uint32_t usm[];
    uint32_t* Ah = usm;
    uint32_t* Bh = usm + A_CHUNK;

    const int tid = threadIdx.x;
    const int wid = tid >> 5, lane = tid & 31;
    const int m0 = blockIdx.y * 128;
    const int b = blockIdx.z;
    const int pix0 = blockIdx.x * 128;

    const float* Amat = g_Gm + ((size_t)b * 256 + m0) * CC;
    const float* X = g_tmp + 2 * (size_t)NTOT + (size_t)b * NPB;  // Vt planar
    const int arows = (m0 == 0) ? 128 : (CC - 128);

    const int wm = (wid & 1) * 4;
    const int wn = (wid >> 1) * 4;

    float acc[4][4][4] = {};

    #pragma unroll 1
    for (int kc = 0; kc < 6; kc++) {
        if (kc) __syncthreads();
        fill_A<false>(Ah, Ah, Amat, kc * 32, arows, tid);
        fill_B<false>(Bh, Bh, X, kc * 32, pix0, tid);
        __syncthreads();
        mma_chunk<false>(acc, Ah, Ah, Bh, Bh, wm, wn, lane);
    }

    int g = lane >> 2, t = lane & 3;
    #pragma unroll
    for (int i = 0; i < 4; i++) {
        #pragma unroll
        for (int half = 0; half < 2; half++) {
            int m = m0 + (wid & 1) * 64 + i * 16 + g + half * 8;
            if (m >= CC) continue;
            float bias = fb[m];
            size_t base = (size_t)b * NPB + (size_t)m * HWW;
            #pragma unroll
            for (int j = 0; j < 4; j++) {
                int pix = pix0 + (wid >> 1) * 32 + j * 8 + 2 * t;
                float2 xv = *(const float2*)&g_xn[base + pix];
                float2 v = make_float2(acc[i][j][half*2+0] + bias + xv.x,
                                       acc[i][j][half*2+1] + bias + xv.y);
                *(float2*)&out[base + pix] = v;
            }
        }
    }
}

// ---------------- depthwise 3x3 SAME (all 3 slots in one launch) ----------------
__global__ __launch_bounds__(256) void dw_kernel(const float* __restrict__ qw, const float* __restrict__ kw,
                                                 const float* __restrict__ vw, const float* __restrict__ qb,
                                                 const float* __restrict__ kb, const float* __restrict__ vb) {
    int slot = blockIdx.y;
    const float* wgt  = (slot == 0) ? qw : (slot == 1) ? kw : vw;
    const float* bias = (slot == 0) ? qb : (slot == 1) ? kb : vb;
    int idx = blockIdx.x * 256 + threadIdx.x;
    const float* in = g_tmp + (size_t)slot * NTOT;
    float* out = g_qkv + (size_t)slot * NTOT;
    int w = idx & (WW - 1);
    int h = (idx >> 7) & (HH - 1);
    int cg = idx >> 14;
    int c = cg % CC;
    const float* ip = in + (size_t)cg * HWW;
    const float* wp = wgt + c * 9;
    float acc = bias[c];
    #pragma unroll
    for (int dy = 0; dy < 3; dy++) {
        int hh = h + dy - 1;
        if (hh < 0 || hh >= HH) continue;
        #pragma unroll
        for (int dx = 0; dx < 3; dx++) {
            int wi = w + dx - 1;
            if (wi < 0 || wi >= WW) continue;
            acc += wp[dy * 3 + dx] * ip[hh * WW + wi];
        }
    }
    out[idx] = acc;
}

// ---------------- spatial transpose of V (torch reshape quirk: H<->W) ----------------
__global__ void transpose_v_kernel() {
    __shared__ float t[32][33];
    int plane = blockIdx.z;
    int h0 = blockIdx.y * 32, w0 = blockIdx.x * 32;
    const float* ip = g_qkv + 2 * (size_t)NTOT + (size_t)plane * HWW;
    float* op = g_tmp + 2 * (size_t)NTOT + (size_t)plane * HWW;
    int tx = threadIdx.x, ty = threadIdx.y;
    #pragma unroll
    for (int i = 0; i < 32; i += 8)
        t[ty + i][tx] = ip[(h0 + ty + i) * WW + w0 + tx];
    __syncthreads();
    #pragma unroll
    for (int i = 0; i < 32; i += 8)
        op[(w0 + ty + i) * WW + h0 + tx] = t[tx][ty + i];
}

// ---------------- per-(b,head) 48x48 Gram ----------------
#define GPITCH 129
__global__ __launch_bounds__(256) void gram_kernel() {
    __shared__ float Ks[SS * GPITCH];
    __shared__ float Qs[SS * GPITCH];
    int bh = blockIdx.x;
    int b = bh / NHEADS, hd = bh % NHEADS;
    int p0 = blockIdx.y * 128;
    const float* Qp = g_qkv + (size_t)b * NPB + (size_t)(hd * SS) * HWW + p0;
    const float* Kp = g_qkv + (size_t)NTOT + (size_t)b * NPB + (size_t)(hd * SS) * HWW + p0;
    int tid = threadIdx.x;
    for (int i = tid; i < SS * 128; i += 256) {
        int s = i >> 7, p = i & 127;
        Ks[s * GPITCH + p] = Kp[(size_t)s * HWW + p];
        Qs[s * GPITCH + p] = Qp[(size_t)s * HWW + p];
    }
    __syncthreads();
    int tx = tid & 15, ty = tid >> 4;
    int s0 = ty * 3, q0 = tx * 3;
    float acc[3][3] = {};
    for (int p = 0; p < 128; p++) {
        float kv0 = Ks[(s0 + 0) * GPITCH + p];
        float kv1 = Ks[(s0 + 1) * GPITCH + p];
        float kv2 = Ks[(s0 + 2) * GPITCH + p];
        float qv0 = Qs[(q0 + 0) * GPITCH + p];
        float qv1 = Qs[(q0 + 1) * GPITCH + p];
        float qv2 = Qs[(q0 + 2) * GPITCH + p];
        acc[0][0] += kv0 * qv0; acc[0][1] += kv0 * qv1; acc[0][2] += kv0 * qv2;
        acc[1][0] += kv1 * qv0; acc[1][1] += kv1 * qv1; acc[1][2] += kv1 * qv2;
        acc[2][0] += kv2 * qv0; acc[2][1] += kv2 * qv1; acc[2][2] += kv2 * qv2;
    }
    float* ap = g_att + (size_t)bh * SS * SS;
    #pragma unroll
    for (int i = 0; i < 3; i++)
        #pragma unroll
        for (int j = 0; j < 3; j++)
            atomicAdd(&ap[(s0 + i) * SS + q0 + j], acc[i][j]);
}

// ---------------- softmax over q ----------------
__global__ void softmax_kernel(const float* __restrict__ alpha) {
    int bh = blockIdx.x;
    int s = threadIdx.x;
    float inva = 1.0f / alpha[0];
    float* row = g_att + ((size_t)bh * SS + s) * SS;
    float mx = -1e30f;
    for (int q = 0; q < SS; q++) mx = fmaxf(mx, row[q] * inva);
    float sum = 0.f;
    for (int q = 0; q < SS; q++) sum += expf(row[q] * inva - mx);
    float rs = 1.0f / sum;
    for (int q = 0; q < SS; q++) row[q] = expf(row[q] * inva - mx) * rs;
}

// ---------------- build fused matrix g_Gm[b][o][cv] ----------------
__global__ void buildG_kernel(const float* __restrict__ fw) {
    int b = blockIdx.x, cv = blockIdx.y;
    int hd = cv / SS, sl = cv % SS;
    __shared__ float arow[SS];
    int o = threadIdx.x;
    if (o < SS) arow[o] = g_att[(((size_t)b * NHEADS + hd) * SS + sl) * SS + o];
    __syncthreads();
    const float* fp = fw + (size_t)o * CC + hd * SS;
    float acc = 0.f;
    #pragma unroll
    for (int q = 0; q < SS; q++) acc += fp[q] * arow[q];
    g_Gm[((size_t)b * 256 + o) * CC + cv] = acc;
}

// ---------------- launch ----------------
extern "C" void kernel_launch(void* const* d_in, const int* in_sizes, int n_in,
                              void* d_out, int out_size) {
    const float* x      = (const float*)d_in[0];
    const float* ln_w   = (const float*)d_in[1];
    const float* ln_b   = (const float*)d_in[2];
    const float* q_pw_w = (const float*)d_in[3];
    const float* q_pw_b = (const float*)d_in[4];
    const float* q_dw_w = (const float*)d_in[5];
    const float* q_dw_b = (const float*)d_in[6];
    const float* k_pw_w = (const float*)d_in[7];
    const float* k_pw_b = (const float*)d_in[8];
    const float* k_dw_w = (const float*)d_in[9];
    const float* k_dw_b = (const float*)d_in[10];
    const float* v_pw_w = (const float*)d_in[11];
    const float* v_pw_b = (const float*)d_in[12];
    const float* v_dw_w = (const float*)d_in[13];
    const float* v_dw_b = (const float*)d_in[14];
    const float* f_w    = (const float*)d_in[15];
    const float* f_b    = (const float*)d_in[16];
    const float* alpha  = (const float*)d_in[17];
    float* out = (float*)d_out;

    cudaFuncSetAttribute(gemm_qkv_mma_kernel<true>,  cudaFuncAttributeMaxDynamicSharedMemorySize, SMEM_3X);
    cudaFuncSetAttribute(gemm_qkv_mma_kernel<false>, cudaFuncAttributeMaxDynamicSharedMemorySize, SMEM_1X);
    cudaFuncSetAttribute(gemm_final_mma_kernel,      cudaFuncAttributeMaxDynamicSharedMemorySize, SMEM_1X);

    prep_weights_kernel<<<(640 * CC + 255) / 256, 256>>>(q_pw_w, k_pw_w, v_pw_w,
                                                         q_pw_b, k_pw_b, v_pw_b);
    zero_att_kernel<<<(BB * NHEADS * SS * SS + 255) / 256, 256>>>();
    ln_kernel<<<(BB * HWW + 255) / 256, 256>>>(x, ln_w, ln_b);
    gemm_qkv_mma_kernel<true><<<dim3(HWW / 128, 3, BB), 256, SMEM_3X>>>(0);
    gemm_qkv_mma_kernel<false><<<dim3(HWW / 128, 2, BB), 256, SMEM_1X>>>(384);
    dw_kernel<<<dim3(NTOT / 256, 3), 256>>>(q_dw_w, k_dw_w, v_dw_w, q_dw_b, k_dw_b, v_dw_b);
    transpose_v_kernel<<<dim3(4, 4, BB * CC), dim3(32, 8)>>>();
    gram_kernel<<<dim3(BB * NHEADS, HWW / 128), 256>>>();
    softmax_kernel<<<BB * NHEADS, SS>>>(alpha);
    buildG_kernel<<<dim3(BB, CC), CC>>>(f_w);
    gemm_final_mma_kernel<<<dim3(HWW / 128, 2, BB), 256, SMEM_1X>>>(f_b, out);
}

// round 8
// speedup vs baseline: 1.4626x; 1.2633x over previous
#include <cuda_runtime.h>
#include <math.h>
#include <stdint.h>

#define BB 8
#define CC 192
#define HH 128
#define WW 128
#define HWW (HH*WW)          // 16384
#define NHEADS 4
#define SS 48
#define NPB (CC*HWW)         // 3145728 per batch per tensor
#define NTOT (BB*NPB)

// ---------------- scratch ----------------
__device__ float g_xn[NTOT];          // layernorm output, channel-planar (residual)
__device__ float g_tmp[3*NTOT];       // pw outputs Qp,Kp,Vp ; slot2 reused as Vt after dw
__device__ float g_qkv[3*NTOT];       // after depthwise: Q,K,V (planar)
__device__ float g_att[BB*NHEADS*SS*SS];
__device__ float g_Gm[BB*256*CC];     // fused matrix per batch, [b][o(pad 256)][cv]
__device__ float g_w3[640*CC];        // stacked pw weights [m(pad 640)][k]
__device__ float g_b3[3*CC];

__device__ __forceinline__ uint32_t tf32_rna(float x) {
    uint32_t u;
    asm("cvt.rna.tf32.f32 %0, %1;" : "=r"(u) : "f"(x));
    return u;
}

// ---------------- weight prep ----------------
__global__ void prep_weights_kernel(const float* __restrict__ qw, const float* __restrict__ kw,
                                    const float* __restrict__ vw, const float* __restrict__ qb,
                                    const float* __restrict__ kb, const float* __restrict__ vb) {
    int idx = blockIdx.x * 256 + threadIdx.x;
    if (idx < 640 * CC) {
        int m = idx / CC, k = idx % CC;
        float v = 0.0f;
        if (m < 576) {
            int slot = m / CC, o = m % CC;
            const float* w = (slot == 0) ? qw : (slot == 1) ? kw : vw;
            v = w[o * CC + k];
        }
        g_w3[idx] = v;
    }
    if (idx < 3 * CC) {
        int i = idx / CC, o = idx % CC;
        const float* bs = (i == 0) ? qb : (i == 1) ? kb : vb;
        g_b3[idx] = bs[o];
    }
}

__global__ void zero_att_kernel() {
    int idx = blockIdx.x * 256 + threadIdx.x;
    if (idx < BB * NHEADS * SS * SS) g_att[idx] = 0.0f;
}

// ---------------- layernorm over channel axis (planar out) ----------------
__global__ __launch_bounds__(256) void ln_kernel(const float* __restrict__ x,
                                                 const float* __restrict__ lw,
                                                 const float* __restrict__ lb) {
    int p = blockIdx.x * 256 + threadIdx.x;
    if (p >= BB * HWW) return;
    int b = p / HWW, sp = p % HWW;
    const float* xp = x + (size_t)b * NPB + sp;
    float s = 0.f, sq = 0.f;
    #pragma unroll 4
    for (int c = 0; c < CC; c++) {
        float v = xp[(size_t)c * HWW];
        s += v; sq += v * v;
    }
    float mu = s * (1.0f / CC);
    float var = sq * (1.0f / CC) - mu * mu;
    float r = rsqrtf(var + 1e-5f);
    float* op = g_xn + (size_t)b * NPB + sp;
    #pragma unroll 4
    for (int c = 0; c < CC; c++) {
        op[(size_t)c * HWW] = (xp[(size_t)c * HWW] - mu) * r * lw[c] + lb[c];
    }
}

// ============== tf32 mma.sync GEMM machinery (1xTF32, double-buffered) ==============
#define A_STRIDE 132
#define B_STRIDE 66
#define A_CHUNK (32 * A_STRIDE)   // 4224 floats
#define B_CHUNK (64 * B_STRIDE)   // 4224 floats
#define BUF_FLOATS (A_CHUNK + B_CHUNK)          // 8448
#define SMEM_DB (2 * BUF_FLOATS * 4)            // 67584 B

#define MMA_TF32(acc, a0, a1, a2, a3, b0, b1) \
    asm volatile( \
        "mma.sync.aligned.m16n8k8.row.col.f32.tf32.tf32.f32 " \
        "{%0,%1,%2,%3}, {%4,%5,%6,%7}, {%8,%9}, {%0,%1,%2,%3};" \
        : "+f"((acc)[0]), "+f"((acc)[1]), "+f"((acc)[2]), "+f"((acc)[3]) \
        : "r"(a0), "r"(a1), "r"(a2), "r"(a3), "r"(b0), "r"(b1))

// A fill: 128 rows x 32 k (direct LDG->cvt->STS; weights are L2-hot)
__device__ __forceinline__ void fill_A(uint32_t* Ah, const float* Amat,
                                       int kbase, int arows, int tid) {
    #pragma unroll
    for (int f = tid; f < 1024; f += 256) {
        int r = f >> 3;
        int k4 = (f & 7) << 2;
        float4 v;
        if (r < arows) v = *(const float4*)&Amat[(size_t)r * CC + kbase + k4];
        else           v = make_float4(0.f, 0.f, 0.f, 0.f);
        int ks = k4 >> 3, hik = (k4 >> 2) & 1;
        int msub = r >> 4, rr = r & 15, g = rr & 7, hir = rr >> 3;
        int base = (msub * 4 + ks) * A_STRIDE + g * 16 + hir + 2 * hik;
        Ah[base + 0]  = tf32_rna(v.x);
        Ah[base + 4]  = tf32_rna(v.y);
        Ah[base + 8]  = tf32_rna(v.z);
        Ah[base + 12] = tf32_rna(v.w);
    }
}

// B stage 1: issue 16 coalesced LDGs into registers
__device__ __forceinline__ void load_B_regs(float breg[16], const float* X,
                                            int kbase, int pix0, int tid) {
    #pragma unroll
    for (int u = 0; u < 16; u++) {
        int f = tid + u * 256;
        int n = f & 127;
        int kk = f >> 7;
        breg[u] = X[(size_t)(kbase + kk) * HWW + pix0 + n];
    }
}
// B stage 2: cvt + STS in fragment order
__device__ __forceinline__ void store_B(uint32_t* Bh, const float breg[16], int tid) {
    #pragma unroll
    for (int u = 0; u < 16; u++) {
        int f = tid + u * 256;
        int n = f & 127;
        int kk = f >> 7;
        int nsub = n >> 3, g = n & 7;
        int ks = kk >> 3, kr = kk & 7;
        int hik = kr >> 2, j = kr & 3;
        Bh[(nsub * 4 + ks) * B_STRIDE + g * 8 + j * 2 + hik] = tf32_rna(breg[u]);
    }
}

__device__ __forceinline__ void mma_chunk(float acc[4][4][4], const uint32_t* Ah,
                                          const uint32_t* Bh, int wm, int wn, int lane) {
    #pragma unroll
    for (int ks = 0; ks < 4; ks++) {
        uint32_t ah[4][4], bh[4][2];
        #pragma unroll
        for (int i = 0; i < 4; i++) {
            uint4 t = *(const uint4*)(Ah + ((wm + i) * 4 + ks) * A_STRIDE + lane * 4);
            ah[i][0] = t.x; ah[i][1] = t.y; ah[i][2] = t.z; ah[i][3] = t.w;
        }
        #pragma unroll
        for (int j = 0; j < 4; j++) {
            uint2 t = *(const uint2*)(Bh + ((wn + j) * 4 + ks) * B_STRIDE + lane * 2);
            bh[j][0] = t.x; bh[j][1] = t.y;
        }
        #pragma unroll
        for (int i = 0; i < 4; i++)
            #pragma unroll
            for (int j = 0; j < 4; j++)
                MMA_TF32(acc[i][j], ah[i][0], ah[i][1], ah[i][2], ah[i][3], bh[j][0], bh[j][1]);
    }
}

// Shared double-buffered mainloop. Amat: [m][k] row-major (CC cols). X: planar [k][pix].
__device__ __forceinline__ void gemm_mainloop(float acc[4][4][4], uint32_t* usm,
                                              const float* Amat, const float* X,
                                              int arows, int pix0, int tid,
                                              int wm, int wn, int lane) {
    float breg[16];
    // prologue: fill buffer 0 with chunk 0
    load_B_regs(breg, X, 0, pix0, tid);
    fill_A(usm, Amat, 0, arows, tid);
    store_B(usm + A_CHUNK, breg, tid);
    __syncthreads();
    #pragma unroll 1
    for (int kc = 0; kc < 6; kc++) {
        uint32_t* cur = usm + (kc & 1) * BUF_FLOATS;
        uint32_t* nxt = usm + ((kc + 1) & 1) * BUF_FLOATS;
        if (kc < 5) load_B_regs(breg, X, (kc + 1) * 32, pix0, tid);  // LDGs hidden by mma
        mma_chunk(acc, cur, cur + A_CHUNK, wm, wn, lane);
        if (kc < 5) {
            fill_A(nxt, Amat, (kc + 1) * 32, arows, tid);
            store_B(nxt + A_CHUNK, breg, tid);
        }
        __syncthreads();
    }
}

// ---------------- QKV pointwise GEMM (all 1xTF32) ----------------
__global__ __launch_bounds__(256, 2) void gemm_qkv_mma_kernel() {
    extern __shared__ uint32_t usm[];
    const int tid = threadIdx.x;
    const int wid = tid >> 5, lane = tid & 31;
    const int m0 = blockIdx.y * 128;
    const int b = blockIdx.z;
    const int pix0 = blockIdx.x * 128;
    const int wm = (wid & 1) * 4;
    const int wn = (wid >> 1) * 4;

    float acc[4][4][4] = {};
    gemm_mainloop(acc, usm, g_w3 + (size_t)m0 * CC, g_xn + (size_t)b * NPB,
                  128, pix0, tid, wm, wn, lane);

    int g = lane >> 2, t = lane & 3;
    #pragma unroll
    for (int i = 0; i < 4; i++) {
        #pragma unroll
        for (int half = 0; half < 2; half++) {
            int m = m0 + (wid & 1) * 64 + i * 16 + g + half * 8;
            if (m >= 576) continue;
            int slot = m / CC, o = m - slot * CC;
            float bias = g_b3[m];
            float* dst = g_tmp + (size_t)slot * NTOT + (size_t)b * NPB + (size_t)o * HWW;
            #pragma unroll
            for (int j = 0; j < 4; j++) {
                int pix = pix0 + (wid >> 1) * 32 + j * 8 + 2 * t;
                float2 v = make_float2(acc[i][j][half*2+0] + bias, acc[i][j][half*2+1] + bias);
                *(float2*)&dst[pix] = v;
            }
        }
    }
}

// ---------------- final GEMM: y = G[b] @ Vt + f_b + xn ----------------
__global__ __launch_bounds__(256, 2) void gemm_final_mma_kernel(const float* __restrict__ fb,
                                                                float* __restrict__ out) {
    extern __shared__ uint32_t usm[];
    const int tid = threadIdx.x;
    const int wid = tid >> 5, lane = tid & 31;
    const int m0 = blockIdx.y * 128;
    const int b = blockIdx.z;
    const int pix0 = blockIdx.x * 128;
    const int arows = (m0 == 0) ? 128 : (CC - 128);
    const int wm = (wid & 1) * 4;
    const int wn = (wid >> 1) * 4;

    float acc[4][4][4] = {};
    gemm_mainloop(acc, usm, g_Gm + ((size_t)b * 256 + m0) * CC,
                  g_tmp + 2 * (size_t)NTOT + (size_t)b * NPB,
                  arows, pix0, tid, wm, wn, lane);

    int g = lane >> 2, t = lane & 3;
    #pragma unroll
    for (int i = 0; i < 4; i++) {
        #pragma unroll
        for (int half = 0; half < 2; half++) {
            int m = m0 + (wid & 1) * 64 + i * 16 + g + half * 8;
            if (m >= CC) continue;
            float bias = fb[m];
            size_t base = (size_t)b * NPB + (size_t)m * HWW;
            #pragma unroll
            for (int j = 0; j < 4; j++) {
                int pix = pix0 + (wid >> 1) * 32 + j * 8 + 2 * t;
                float2 xv = *(const float2*)&g_xn[base + pix];
                float2 v = make_float2(acc[i][j][half*2+0] + bias + xv.x,
                                       acc[i][j][half*2+1] + bias + xv.y);
                *(float2*)&out[base + pix] = v;
            }
        }
    }
}

// ---------------- depthwise 3x3 SAME (all 3 slots in one launch) ----------------
__global__ __launch_bounds__(256) void dw_kernel(const float* __restrict__ qw, const float* __restrict__ kw,
                                                 const float* __restrict__ vw, const float* __restrict__ qb,
                                                 const float* __restrict__ kb, const float* __restrict__ vb) {
    int slot = blockIdx.y;
    const float* wgt  = (slot == 0) ? qw : (slot == 1) ? kw : vw;
    const float* bias = (slot == 0) ? qb : (slot == 1) ? kb : vb;
    int idx = blockIdx.x * 256 + threadIdx.x;
    const float* in = g_tmp + (size_t)slot * NTOT;
    float* out = g_qkv + (size_t)slot * NTOT;
    int w = idx & (WW - 1);
    int h = (idx >> 7) & (HH - 1);
    int cg = idx >> 14;
    int c = cg % CC;
    const float* ip = in + (size_t)cg * HWW;
    const float* wp = wgt + c * 9;
    float acc = bias[c];
    #pragma unroll
    for (int dy = 0; dy < 3; dy++) {
        int hh = h + dy - 1;
        if (hh < 0 || hh >= HH) continue;
        #pragma unroll
        for (int dx = 0; dx < 3; dx++) {
            int wi = w + dx - 1;
            if (wi < 0 || wi >= WW) continue;
            acc += wp[dy * 3 + dx] * ip[hh * WW + wi];
        }
    }
    out[idx] = acc;
}

// ---------------- spatial transpose of V (torch reshape quirk: H<->W) ----------------
__global__ void transpose_v_kernel() {
    __shared__ float t[32][33];
    int plane = blockIdx.z;
    int h0 = blockIdx.y * 32, w0 = blockIdx.x * 32;
    const float* ip = g_qkv + 2 * (size_t)NTOT + (size_t)plane * HWW;
    float* op = g_tmp + 2 * (size_t)NTOT + (size_t)plane * HWW;
    int tx = threadIdx.x, ty = threadIdx.y;
    #pragma unroll
    for (int i = 0; i < 32; i += 8)
        t[ty + i][tx] = ip[(h0 + ty + i) * WW + w0 + tx];
    __syncthreads();
    #pragma unroll
    for (int i = 0; i < 32; i += 8)
        op[(w0 + ty + i) * WW + h0 + tx] = t[tx][ty + i];
}

// ---------------- per-(b,head) 48x48 Gram ----------------
#define GPITCH 129
__global__ __launch_bounds__(256) void gram_kernel() {
    __shared__ float Ks[SS * GPITCH];
    __shared__ float Qs[SS * GPITCH];
    int bh = blockIdx.x;
    int b = bh / NHEADS, hd = bh % NHEADS;
    int p0 = blockIdx.y * 128;
    const float* Qp = g_qkv + (size_t)b * NPB + (size_t)(hd * SS) * HWW + p0;
    const float* Kp = g_qkv + (size_t)NTOT + (size_t)b * NPB + (size_t)(hd * SS) * HWW + p0;
    int tid = threadIdx.x;
    for (int i = tid; i < SS * 128; i += 256) {
        int s = i >> 7, p = i & 127;
        Ks[s * GPITCH + p] = Kp[(size_t)s * HWW + p];
        Qs[s * GPITCH + p] = Qp[(size_t)s * HWW + p];
    }
    __syncthreads();
    int tx = tid & 15, ty = tid >> 4;
    int s0 = ty * 3, q0 = tx * 3;
    float acc[3][3] = {};
    for (int p = 0; p < 128; p++) {
        float kv0 = Ks[(s0 + 0) * GPITCH + p];
        float kv1 = Ks[(s0 + 1) * GPITCH + p];
        float kv2 = Ks[(s0 + 2) * GPITCH + p];
        float qv0 = Qs[(q0 + 0) * GPITCH + p];
        float qv1 = Qs[(q0 + 1) * GPITCH + p];
        float qv2 = Qs[(q0 + 2) * GPITCH + p];
        acc[0][0] += kv0 * qv0; acc[0][1] += kv0 * qv1; acc[0][2] += kv0 * qv2;
        acc[1][0] += kv1 * qv0; acc[1][1] += kv1 * qv1; acc[1][2] += kv1 * qv2;
        acc[2][0] += kv2 * qv0; acc[2][1] += kv2 * qv1; acc[2][2] += kv2 * qv2;
    }
    float* ap = g_att + (size_t)bh * SS * SS;
    #pragma unroll
    for (int i = 0; i < 3; i++)
        #pragma unroll
        for (int j = 0; j < 3; j++)
            atomicAdd(&ap[(s0 + i) * SS + q0 + j], acc[i][j]);
}

// ---------------- softmax over q ----------------
__global__ void softmax_kernel(const float* __restrict__ alpha) {
    int bh = blockIdx.x;
    int s = threadIdx.x;
    float inva = 1.0f / alpha[0];
    float* row = g_att + ((size_t)bh * SS + s) * SS;
    float mx = -1e30f;
    for (int q = 0; q < SS; q++) mx = fmaxf(mx, row[q] * inva);
    float sum = 0.f;
    for (int q = 0; q < SS; q++) sum += expf(row[q] * inva - mx);
    float rs = 1.0f / sum;
    for (int q = 0; q < SS; q++) row[q] = expf(row[q] * inva - mx) * rs;
}

// ---------------- build fused matrix g_Gm[b][o][cv] ----------------
__global__ void buildG_kernel(const float* __restrict__ fw) {
    int b = blockIdx.x, cv = blockIdx.y;
    int hd = cv / SS, sl = cv % SS;
    __shared__ float arow[SS];
    int o = threadIdx.x;
    if (o < SS) arow[o] = g_att[(((size_t)b * NHEADS + hd) * SS + sl) * SS + o];
    __syncthreads();
    const float* fp = fw + (size_t)o * CC + hd * SS;
    float acc = 0.f;
    #pragma unroll
    for (int q = 0; q < SS; q++) acc += fp[q] * arow[q];
    g_Gm[((size_t)b * 256 + o) * CC + cv] = acc;
}

// ---------------- launch ----------------
extern "C" void kernel_launch(void* const* d_in, const int* in_sizes, int n_in,
                              void* d_out, int out_size) {
    const float* x      = (const float*)d_in[0];
    const float* ln_w   = (const float*)d_in[1];
    const float* ln_b   = (const float*)d_in[2];
    const float* q_pw_w = (const float*)d_in[3];
    const float* q_pw_b = (const float*)d_in[4];
    const float* q_dw_w = (const float*)d_in[5];
    const float* q_dw_b = (const float*)d_in[6];
    const float* k_pw_w = (const float*)d_in[7];
    const float* k_pw_b = (const float*)d_in[8];
    const float* k_dw_w = (const float*)d_in[9];
    const float* k_dw_b = (const float*)d_in[10];
    const float* v_pw_w = (const float*)d_in[11];
    const float* v_pw_b = (const float*)d_in[12];
    const float* v_dw_w = (const float*)d_in[13];
    const float* v_dw_b = (const float*)d_in[14];
    const float* f_w    = (const float*)d_in[15];
    const float* f_b    = (const float*)d_in[16];
    const float* alpha  = (const float*)d_in[17];
    float* out = (float*)d_out;

    cudaFuncSetAttribute(gemm_qkv_mma_kernel,   cudaFuncAttributeMaxDynamicSharedMemorySize, SMEM_DB);
    cudaFuncSetAttribute(gemm_final_mma_kernel, cudaFuncAttributeMaxDynamicSharedMemorySize, SMEM_DB);

    prep_weights_kernel<<<(640 * CC + 255) / 256, 256>>>(q_pw_w, k_pw_w, v_pw_w,
                                                         q_pw_b, k_pw_b, v_pw_b);
    zero_att_kernel<<<(BB * NHEADS * SS * SS + 255) / 256, 256>>>();
    ln_kernel<<<(BB * HWW + 255) / 256, 256>>>(x, ln_w, ln_b);
    gemm_qkv_mma_kernel<<<dim3(HWW / 128, 5, BB), 256, SMEM_DB>>>();
    dw_kernel<<<dim3(NTOT / 256, 3), 256>>>(q_dw_w, k_dw_w, v_dw_w, q_dw_b, k_dw_b, v_dw_b);
    transpose_v_kernel<<<dim3(4, 4, BB * CC), dim3(32, 8)>>>();
    gram_kernel<<<dim3(BB * NHEADS, HWW / 128), 256>>>();
    softmax_kernel<<<BB * NHEADS, SS>>>(alpha);
    buildG_kernel<<<dim3(BB, CC), CC>>>(f_w);
    gemm_final_mma_kernel<<<dim3(HWW / 128, 2, BB), 256, SMEM_DB>>>(f_b, out);
}

// round 9
// speedup vs baseline: 2.0978x; 1.4343x over previous
#include <cuda_runtime.h>
#include <math.h>
#include <stdint.h>

#define BB 8
#define CC 192
#define HH 128
#define WW 128
#define HWW (HH*WW)          // 16384
#define NHEADS 4
#define SS 48
#define NPB (CC*HWW)         // 3145728 per batch per tensor
#define NTOT (BB*NPB)

// ---------------- scratch ----------------
__device__ float g_xn[NTOT];          // layernorm output, channel-planar (residual)
__device__ float g_tmp[3*NTOT];       // pw outputs Qp,Kp,Vp ; slot2 reused as Vt after dw
__device__ float g_qkv[3*NTOT];       // after depthwise: Q,K,V (planar)
__device__ float g_att[BB*NHEADS*SS*SS];
__device__ float g_Gm[BB*256*CC];     // fused matrix per batch, [b][o(pad 256)][cv]
__device__ float g_w3[640*CC];        // stacked pw weights [m(pad 640)][k]
__device__ float g_b3[3*CC];

// pack two fp32 into bf16x2 (lo = first k, hi = second k)
__device__ __forceinline__ uint32_t bf2(float lo, float hi) {
    uint32_t d;
    asm("cvt.rn.bf16x2.f32 %0, %1, %2;" : "=r"(d) : "f"(hi), "f"(lo));
    return d;
}

// ---------------- weight prep ----------------
__global__ void prep_weights_kernel(const float* __restrict__ qw, const float* __restrict__ kw,
                                    const float* __restrict__ vw, const float* __restrict__ qb,
                                    const float* __restrict__ kb, const float* __restrict__ vb) {
    int idx = blockIdx.x * 256 + threadIdx.x;
    if (idx < 640 * CC) {
        int m = idx / CC, k = idx % CC;
        float v = 0.0f;
        if (m < 576) {
            int slot = m / CC, o = m % CC;
            const float* w = (slot == 0) ? qw : (slot == 1) ? kw : vw;
            v = w[o * CC + k];
        }
        g_w3[idx] = v;
    }
    if (idx < 3 * CC) {
        int i = idx / CC, o = idx % CC;
        const float* bs = (i == 0) ? qb : (i == 1) ? kb : vb;
        g_b3[idx] = bs[o];
    }
}

__global__ void zero_att_kernel() {
    int idx = blockIdx.x * 256 + threadIdx.x;
    if (idx < BB * NHEADS * SS * SS) g_att[idx] = 0.0f;
}

// ---------------- layernorm over channel axis (planar out) ----------------
__global__ __launch_bounds__(256) void ln_kernel(const float* __restrict__ x,
                                                 const float* __restrict__ lw,
                                                 const float* __restrict__ lb) {
    int p = blockIdx.x * 256 + threadIdx.x;
    if (p >= BB * HWW) return;
    int b = p / HWW, sp = p % HWW;
    const float* xp = x + (size_t)b * NPB + sp;
    float s = 0.f, sq = 0.f;
    #pragma unroll 4
    for (int c = 0; c < CC; c++) {
        float v = xp[(size_t)c * HWW];
        s += v; sq += v * v;
    }
    float mu = s * (1.0f / CC);
    float var = sq * (1.0f / CC) - mu * mu;
    float r = rsqrtf(var + 1e-5f);
    float* op = g_xn + (size_t)b * NPB + sp;
    #pragma unroll 4
    for (int c = 0; c < CC; c++) {
        op[(size_t)c * HWW] = (xp[(size_t)c * HWW] - mu) * r * lw[c] + lb[c];
    }
}

// ============== bf16 mma.sync GEMM machinery (m16n8k16, double-buffered) ==============
// K-chunk 32 = 2 ksteps of k16.
// A block (msub, ks): [lane 0..31][reg 0..3] u32, stride A_BLK. lane = t identity.
// B block (nsub, ks): [lane 0..31][reg 0..1] u32, stride B_BLK. lane = t identity.
#define A_BLK 132
#define B_BLK 70
#define A_CH (16 * A_BLK)     // 2112 u32
#define B_CH (32 * B_BLK)     // 2240 u32
#define BUF_U32 (A_CH + B_CH) // 4352
#define SMEM_DB (2 * BUF_U32 * 4)   // 34816 B

#define MMA_BF16(acc, a0, a1, a2, a3, b0, b1) \
    asm volatile( \
        "mma.sync.aligned.m16n8k16.row.col.f32.bf16.bf16.f32 " \
        "{%0,%1,%2,%3}, {%4,%5,%6,%7}, {%8,%9}, {%0,%1,%2,%3};" \
        : "+f"((acc)[0]), "+f"((acc)[1]), "+f"((acc)[2]), "+f"((acc)[3]) \
        : "r"(a0), "r"(a1), "r"(a2), "r"(a3), "r"(b0), "r"(b1))

// A fill: 128 rows x 32 k. unit = (koq, g, ks, msub); 2 units/thread.
__device__ __forceinline__ void fill_A(uint32_t* Ab, const float* Amat,
                                       int kbase, int arows, int tid) {
    #pragma unroll
    for (int u = 0; u < 2; u++) {
        int unit = tid + u * 256;
        int koq  = unit & 3;            // float4 index within k16
        int g    = (unit >> 2) & 7;
        int ks   = (unit >> 5) & 1;
        int msub = unit >> 6;           // 0..7
        int r0 = msub * 16 + g;
        int koff = koq * 4;
        int kk = kbase + ks * 16 + koff;
        float4 v0 = make_float4(0.f,0.f,0.f,0.f), v1 = v0;
        if (r0 < arows)     v0 = *(const float4*)&Amat[(size_t)r0 * CC + kk];
        if (r0 + 8 < arows) v1 = *(const float4*)&Amat[(size_t)(r0 + 8) * CC + kk];
        int P0 = koff >> 1;             // 0,2,4,6
        int lane0 = g * 4 + (P0 & 3);
        int regbase = (koff >= 8) ? 2 : 0;
        uint32_t* blk = Ab + (msub * 2 + ks) * A_BLK;
        *(uint2*)(blk + lane0 * 4 + regbase)       = make_uint2(bf2(v0.x, v0.y), bf2(v1.x, v1.y));
        *(uint2*)(blk + (lane0 + 1) * 4 + regbase) = make_uint2(bf2(v0.z, v0.w), bf2(v1.z, v1.w));
    }
}

// B stage 1: 4 coalesced LDG.128 into registers (rows 2kp,2kp+1,2kp+8,2kp+9 of this thread's ks)
__device__ __forceinline__ void load_B4(float4 v[4], const float* X,
                                        int kbase, int pix0, int tid) {
    int n4 = (tid & 31) * 4;
    int kp = (tid >> 5) & 3;
    int ks = tid >> 7;
    const float* base = X + (size_t)(kbase + ks * 16) * HWW + pix0 + n4;
    v[0] = *(const float4*)(base + (size_t)(2 * kp) * HWW);
    v[1] = *(const float4*)(base + (size_t)(2 * kp + 1) * HWW);
    v[2] = *(const float4*)(base + (size_t)(2 * kp + 8) * HWW);
    v[3] = *(const float4*)(base + (size_t)(2 * kp + 9) * HWW);
}
// B stage 2: pack + 4 STS.64 in fragment order
__device__ __forceinline__ void store_B(uint32_t* Bb, const float4 v[4], int tid) {
    int n4 = (tid & 31) * 4;
    int kp = (tid >> 5) & 3;
    int ks = tid >> 7;
    const float* e0 = (const float*)&v[0];
    const float* e1 = (const float*)&v[1];
    const float* e2 = (const float*)&v[2];
    const float* e3 = (const float*)&v[3];
    #pragma unroll
    for (int q = 0; q < 4; q++) {
        int n = n4 + q;
        int lane = (n & 7) * 4 + kp;
        uint32_t* blk = Bb + ((n >> 3) * 2 + ks) * B_BLK;
        *(uint2*)(blk + lane * 2) = make_uint2(bf2(e0[q], e1[q]), bf2(e2[q], e3[q]));
    }
}

__device__ __forceinline__ void mma_chunk(float acc[4][4][4], const uint32_t* Ab,
                                          const uint32_t* Bb, int wm, int wn, int lane) {
    #pragma unroll
    for (int ks = 0; ks < 2; ks++) {
        uint32_t ah[4][4], bh[4][2];
        #pragma unroll
        for (int i = 0; i < 4; i++) {
            uint4 t = *(const uint4*)(Ab + ((wm + i) * 2 + ks) * A_BLK + lane * 4);
            ah[i][0] = t.x; ah[i][1] = t.y; ah[i][2] = t.z; ah[i][3] = t.w;
        }
        #pragma unroll
        for (int j = 0; j < 4; j++) {
            uint2 t = *(const uint2*)(Bb + ((wn + j) * 2 + ks) * B_BLK + lane * 2);
            bh[j][0] = t.x; bh[j][1] = t.y;
        }
        #pragma unroll
        for (int i = 0; i < 4; i++)
            #pragma unroll
            for (int j = 0; j < 4; j++)
                MMA_BF16(acc[i][j], ah[i][0], ah[i][1], ah[i][2], ah[i][3], bh[j][0], bh[j][1]);
    }
}

// Shared double-buffered mainloop. Amat: [m][k] row-major (CC cols). X: planar [k][pix].
__device__ __forceinline__ void gemm_mainloop(float acc[4][4][4], uint32_t* usm,
                                              const float* Amat, const float* X,
                                              int arows, int pix0, int tid,
                                              int wm, int wn, int lane) {
    float4 breg[4];
    load_B4(breg, X, 0, pix0, tid);
    fill_A(usm, Amat, 0, arows, tid);
    store_B(usm + A_CH, breg, tid);
    __syncthreads();
    #pragma unroll 1
    for (int kc = 0; kc < 6; kc++) {
        uint32_t* cur = usm + (kc & 1) * BUF_U32;
        uint32_t* nxt = usm + ((kc + 1) & 1) * BUF_U32;
        if (kc < 5) load_B4(breg, X, (kc + 1) * 32, pix0, tid);  // LDGs hidden by mma
        mma_chunk(acc, cur, cur + A_CH, wm, wn, lane);
        if (kc < 5) {
            fill_A(nxt, Amat, (kc + 1) * 32, arows, tid);
            store_B(nxt + A_CH, breg, tid);
        }
        __syncthreads();
    }
}

// ---------------- QKV pointwise GEMM ----------------
__global__ __launch_bounds__(256, 2) void gemm_qkv_mma_kernel() {
    extern __shared__ uint32_t usm[];
    const int tid = threadIdx.x;
    const int wid = tid >> 5, lane = tid & 31;
    const int m0 = blockIdx.x * 128;        // m-major: adjacent CTAs share B tile (L2)
    const int pix0 = blockIdx.y * 128;
    const int b = blockIdx.z;
    const int wm = (wid & 1) * 4;
    const int wn = (wid >> 1) * 4;

    float acc[4][4][4] = {};
    gemm_mainloop(acc, usm, g_w3 + (size_t)m0 * CC, g_xn + (size_t)b * NPB,
                  128, pix0, tid, wm, wn, lane);

    int g = lane >> 2, t = lane & 3;
    #pragma unroll
    for (int i = 0; i < 4; i++) {
        #pragma unroll
        for (int half = 0; half < 2; half++) {
            int m = m0 + (wid & 1) * 64 + i * 16 + g + half * 8;
            if (m >= 576) continue;
            int slot = m / CC, o = m - slot * CC;
            float bias = g_b3[m];
            float* dst = g_tmp + (size_t)slot * NTOT + (size_t)b * NPB + (size_t)o * HWW;
            #pragma unroll
            for (int j = 0; j < 4; j++) {
                int pix = pix0 + (wid >> 1) * 32 + j * 8 + 2 * t;
                float2 v = make_float2(acc[i][j][half*2+0] + bias, acc[i][j][half*2+1] + bias);
                *(float2*)&dst[pix] = v;
            }
        }
    }
}

// ---------------- final GEMM: y = G[b] @ Vt + f_b + xn ----------------
__global__ __launch_bounds__(256, 2) void gemm_final_mma_kernel(const float* __restrict__ fb,
                                                                float* __restrict__ out) {
    extern __shared__ uint32_t usm[];
    const int tid = threadIdx.x;
    const int wid = tid >> 5, lane = tid & 31;
    const int m0 = blockIdx.x * 128;
    const int pix0 = blockIdx.y * 128;
    const int b = blockIdx.z;
    const int arows = (m0 == 0) ? 128 : (CC - 128);
    const int wm = (wid & 1) * 4;
    const int wn = (wid >> 1) * 4;

    float acc[4][4][4] = {};
    gemm_mainloop(acc, usm, g_Gm + ((size_t)b * 256 + m0) * CC,
                  g_tmp + 2 * (size_t)NTOT + (size_t)b * NPB,
                  arows, pix0, tid, wm, wn, lane);

    int g = lane >> 2, t = lane & 3;
    #pragma unroll
    for (int i = 0; i < 4; i++) {
        #pragma unroll
        for (int half = 0; half < 2; half++) {
            int m = m0 + (wid & 1) * 64 + i * 16 + g + half * 8;
            if (m >= CC) continue;
            float bias = fb[m];
            size_t base = (size_t)b * NPB + (size_t)m * HWW;
            #pragma unroll
            for (int j = 0; j < 4; j++) {
                int pix = pix0 + (wid >> 1) * 32 + j * 8 + 2 * t;
                float2 xv = *(const float2*)&g_xn[base + pix];
                float2 v = make_float2(acc[i][j][half*2+0] + bias + xv.x,
                                       acc[i][j][half*2+1] + bias + xv.y);
                *(float2*)&out[base + pix] = v;
            }
        }
    }
}

// ---------------- depthwise 3x3 SAME, 4 pixels/thread ----------------
__global__ __launch_bounds__(256) void dw_kernel(const float* __restrict__ qw, const float* __restrict__ kw,
                                                 const float* __restrict__ vw, const float* __restrict__ qb,
                                                 const float* __restrict__ kb, const float* __restrict__ vb) {
    int slot = blockIdx.y;
    const float* wgt  = (slot == 0) ? qw : (slot == 1) ? kw : vw;
    const float* bias = (slot == 0) ? qb : (slot == 1) ? kb : vb;
    int idx = blockIdx.x * 256 + threadIdx.x;   // over NTOT/4
    const float* in = g_tmp + (size_t)slot * NTOT;
    float* out = g_qkv + (size_t)slot * NTOT;
    int w4 = (idx & 31) * 4;
    int h = (idx >> 5) & (HH - 1);
    int cg = idx >> 12;                          // b*C + c
    int c = cg % CC;
    const float* ip = in + (size_t)cg * HWW;
    const float* wp = wgt + c * 9;
    float bv = bias[c];
    float a0 = bv, a1 = bv, a2 = bv, a3 = bv;
    #pragma unroll
    for (int dy = 0; dy < 3; dy++) {
        int hh = h + dy - 1;
        if (hh < 0 || hh >= HH) continue;
        const float* row = ip + hh * WW + w4;
        float4 m = *(const float4*)row;
        float lf = (w4 > 0)   ? row[-1] : 0.f;
        float rt = (w4 < 124) ? row[4]  : 0.f;
        float k0 = wp[dy*3], k1 = wp[dy*3+1], k2 = wp[dy*3+2];
        a0 += k0*lf  + k1*m.x + k2*m.y;
        a1 += k0*m.x + k1*m.y + k2*m.z;
        a2 += k0*m.y + k1*m.z + k2*m.w;
        a3 += k0*m.z + k1*m.w + k2*rt;
    }
    *(float4*)&out[(size_t)cg * HWW + h * WW + w4] = make_float4(a0, a1, a2, a3);
}

// ---------------- spatial transpose of V (torch reshape quirk: H<->W) ----------------
__global__ void transpose_v_kernel() {
    __shared__ float t[32][33];
    int plane = blockIdx.z;
    int h0 = blockIdx.y * 32, w0 = blockIdx.x * 32;
    const float* ip = g_qkv + 2 * (size_t)NTOT + (size_t)plane * HWW;
    float* op = g_tmp + 2 * (size_t)NTOT + (size_t)plane * HWW;
    int tx = threadIdx.x, ty = threadIdx.y;
    #pragma unroll
    for (int i = 0; i < 32; i += 8)
        t[ty + i][tx] = ip[(h0 + ty + i) * WW + w0 + tx];
    __syncthreads();
    #pragma unroll
    for (int i = 0; i < 32; i += 8)
        op[(w0 + ty + i) * WW + h0 + tx] = t[tx][ty + i];
}

// ---------------- per-(b,head) 48x48 Gram ----------------
#define GPITCH 129
__global__ __launch_bounds__(256) void gram_kernel() {
    __shared__ float Ks[SS * GPITCH];
    __shared__ float Qs[SS * GPITCH];
    int bh = blockIdx.x;
    int b = bh / NHEADS, hd = bh % NHEADS;
    int p0 = blockIdx.y * 128;
    const float* Qp = g_qkv + (size_t)b * NPB + (size_t)(hd * SS) * HWW + p0;
    const float* Kp = g_qkv + (size_t)NTOT + (size_t)b * NPB + (size_t)(hd * SS) * HWW + p0;
    int tid = threadIdx.x;
    for (int i = tid; i < SS * 128; i += 256) {
        int s = i >> 7, p = i & 127;
        Ks[s * GPITCH + p] = Kp[(size_t)s * HWW + p];
        Qs[s * GPITCH + p] = Qp[(size_t)s * HWW + p];
    }
    __syncthreads();
    int tx = tid & 15, ty = tid >> 4;
    int s0 = ty * 3, q0 = tx * 3;
    float acc[3][3] = {};
    for (int p = 0; p < 128; p++) {
        float kv0 = Ks[(s0 + 0) * GPITCH + p];
        float kv1 = Ks[(s0 + 1) * GPITCH + p];
        float kv2 = Ks[(s0 + 2) * GPITCH + p];
        float qv0 = Qs[(q0 + 0) * GPITCH + p];
        float qv1 = Qs[(q0 + 1) * GPITCH + p];
        float qv2 = Qs[(q0 + 2) * GPITCH + p];
        acc[0][0] += kv0 * qv0; acc[0][1] += kv0 * qv1; acc[0][2] += kv0 * qv2;
        acc[1][0] += kv1 * qv0; acc[1][1] += kv1 * qv1; acc[1][2] += kv1 * qv2;
        acc[2][0] += kv2 * qv0; acc[2][1] += kv2 * qv1; acc[2][2] += kv2 * qv2;
    }
    float* ap = g_att + (size_t)bh * SS * SS;
    #pragma unroll
    for (int i = 0; i < 3; i++)
        #pragma unroll
        for (int j = 0; j < 3; j++)
            atomicAdd(&ap[(s0 + i) * SS + q0 + j], acc[i][j]);
}

// ---------------- softmax over q ----------------
__global__ void softmax_kernel(const float* __restrict__ alpha) {
    int bh = blockIdx.x;
    int s = threadIdx.x;
    float inva = 1.0f / alpha[0];
    float* row = g_att + ((size_t)bh * SS + s) * SS;
    float mx = -1e30f;
    for (int q = 0; q < SS; q++) mx = fmaxf(mx, row[q] * inva);
    float sum = 0.f;
    for (int q = 0; q < SS; q++) sum += expf(row[q] * inva - mx);
    float rs = 1.0f / sum;
    for (int q = 0; q < SS; q++) row[q] = expf(row[q] * inva - mx) * rs;
}

// ---------------- build fused matrix g_Gm[b][o][cv] ----------------
__global__ void buildG_kernel(const float* __restrict__ fw) {
    int b = blockIdx.x, cv = blockIdx.y;
    int hd = cv / SS, sl = cv % SS;
    __shared__ float arow[SS];
    int o = threadIdx.x;
    if (o < SS) arow[o] = g_att[(((size_t)b * NHEADS + hd) * SS + sl) * SS + o];
    __syncthreads();
    const float* fp = fw + (size_t)o * CC + hd * SS;
    float acc = 0.f;
    #pragma unroll
    for (int q = 0; q < SS; q++) acc += fp[q] * arow[q];
    g_Gm[((size_t)b * 256 + o) * CC + cv] = acc;
}

// ---------------- launch ----------------
extern "C" void kernel_launch(void* const* d_in, const int* in_sizes, int n_in,
                              void* d_out, int out_size) {
    const float* x      = (const float*)d_in[0];
    const float* ln_w   = (const float*)d_in[1];
    const float* ln_b   = (const float*)d_in[2];
    const float* q_pw_w = (const float*)d_in[3];
    const float* q_pw_b = (const float*)d_in[4];
    const float* q_dw_w = (const float*)d_in[5];
    const float* q_dw_b = (const float*)d_in[6];
    const float* k_pw_w = (const float*)d_in[7];
    const float* k_pw_b = (const float*)d_in[8];
    const float* k_dw_w = (const float*)d_in[9];
    const float* k_dw_b = (const float*)d_in[10];
    const float* v_pw_w = (const float*)d_in[11];
    const float* v_pw_b = (const float*)d_in[12];
    const float* v_dw_w = (const float*)d_in[13];
    const float* v_dw_b = (const float*)d_in[14];
    const float* f_w    = (const float*)d_in[15];
    const float* f_b    = (const float*)d_in[16];
    const float* alpha  = (const float*)d_in[17];
    float* out = (float*)d_out;

    cudaFuncSetAttribute(gemm_qkv_mma_kernel,   cudaFuncAttributeMaxDynamicSharedMemorySize, SMEM_DB);
    cudaFuncSetAttribute(gemm_final_mma_kernel, cudaFuncAttributeMaxDynamicSharedMemorySize, SMEM_DB);

    prep_weights_kernel<<<(640 * CC + 255) / 256, 256>>>(q_pw_w, k_pw_w, v_pw_w,
                                                         q_pw_b, k_pw_b, v_pw_b);
    zero_att_kernel<<<(BB * NHEADS * SS * SS + 255) / 256, 256>>>();
    ln_kernel<<<(BB * HWW + 255) / 256, 256>>>(x, ln_w, ln_b);
    gemm_qkv_mma_kernel<<<dim3(5, HWW / 128, BB), 256, SMEM_DB>>>();
    dw_kernel<<<dim3(NTOT / 1024, 3), 256>>>(q_dw_w, k_dw_w, v_dw_w, q_dw_b, k_dw_b, v_dw_b);
    transpose_v_kernel<<<dim3(4, 4, BB * CC), dim3(32, 8)>>>();
    gram_kernel<<<dim3(BB * NHEADS, HWW / 128), 256>>>();
    softmax_kernel<<<BB * NHEADS, SS>>>(alpha);
    buildG_kernel<<<dim3(BB, CC), CC>>>(f_w);
    gemm_final_mma_kernel<<<dim3(2, HWW / 128, BB), 256, SMEM_DB>>>(f_b, out);
}

// round 10
// speedup vs baseline: 2.3510x; 1.1207x over previous
#include <cuda_runtime.h>
#include <math.h>
#include <stdint.h>

#define BB 8
#define CC 192
#define HH 128
#define WW 128
#define HWW (HH*WW)          // 16384
#define NHEADS 4
#define SS 48
#define NPB (CC*HWW)         // 3145728 per batch per tensor
#define NTOT (BB*NPB)

// ---------------- scratch ----------------
__device__ float g_mu[BB*HWW];        // per-pixel LN mean
__device__ float g_rs[BB*HWW];        // per-pixel LN rsqrt(var+eps)
__device__ float g_tmp[3*NTOT];       // pw outputs Qp,Kp,Vp
__device__ float g_qkv[3*NTOT];       // after dw: Q,K planar; slot2 = Vt (spatially transposed V)
__device__ float g_att[BB*NHEADS*SS*SS];
__device__ float g_Gm[BB*256*CC];     // fused matrix per batch, [b][o(pad 256)][cv]
__device__ float g_w3[640*CC];        // stacked pw weights [m(pad 640)][k], fp32
__device__ uint32_t g_w3f[5*6*2048];  // pre-formatted bf16 A fragments [mb][kc][blk*128+lane*4+reg]
__device__ float g_b3[3*CC];

// pack two fp32 into bf16x2 (lo = first k, hi = second k)
__device__ __forceinline__ uint32_t bf2(float lo, float hi) {
    uint32_t d;
    asm("cvt.rn.bf16x2.f32 %0, %1, %2;" : "=r"(d) : "f"(hi), "f"(lo));
    return d;
}

// ---------------- weight prep ----------------
__global__ void prep_weights_kernel(const float* __restrict__ qw, const float* __restrict__ kw,
                                    const float* __restrict__ vw, const float* __restrict__ qb,
                                    const float* __restrict__ kb, const float* __restrict__ vb) {
    int idx = blockIdx.x * 256 + threadIdx.x;
    if (idx < 640 * CC) {
        int m = idx / CC, k = idx % CC;
        float v = 0.0f;
        if (m < 576) {
            int slot = m / CC, o = m % CC;
            const float* w = (slot == 0) ? qw : (slot == 1) ? kw : vw;
            v = w[o * CC + k];
        }
        g_w3[idx] = v;
    }
    if (idx < 3 * CC) {
        int i = idx / CC, o = idx % CC;
        const float* bs = (i == 0) ? qb : (i == 1) ? kb : vb;
        g_b3[idx] = bs[o];
    }
}

// format g_w3 -> bf16 fragment layout. grid (5,6), 256 thr
__global__ void prep_frag_kernel() {
    int mb = blockIdx.x, kc = blockIdx.y;
    int tid = threadIdx.x;
    uint32_t* dst = g_w3f + (mb * 6 + kc) * 2048;
    #pragma unroll
    for (int u = 0; u < 2; u++) {
        int unit = tid + u * 256;
        int koq  = unit & 3;
        int g    = (unit >> 2) & 7;
        int ks   = (unit >> 5) & 1;
        int msub = unit >> 6;
        int r0 = mb * 128 + msub * 16 + g;
        int koff = koq * 4;
        int kk = kc * 32 + ks * 16 + koff;
        float4 v0 = *(const float4*)&g_w3[(size_t)r0 * CC + kk];
        float4 v1 = *(const float4*)&g_w3[(size_t)(r0 + 8) * CC + kk];
        int lane0 = g * 4 + ((koq * 2) & 3);
        int regbase = (koff >= 8) ? 2 : 0;
        uint32_t* blk = dst + (msub * 2 + ks) * 128;
        *(uint2*)(blk + lane0 * 4 + regbase)       = make_uint2(bf2(v0.x, v0.y), bf2(v1.x, v1.y));
        *(uint2*)(blk + (lane0 + 1) * 4 + regbase) = make_uint2(bf2(v0.z, v0.w), bf2(v1.z, v1.w));
    }
}

__global__ void zero_att_kernel() {
    int idx = blockIdx.x * 256 + threadIdx.x;
    if (idx < BB * NHEADS * SS * SS) g_att[idx] = 0.0f;
}

// ---------------- LN stats only (mu, rsig per pixel) ----------------
__global__ __launch_bounds__(256) void ln_stats_kernel(const float* __restrict__ x) {
    int p = blockIdx.x * 256 + threadIdx.x;
    if (p >= BB * HWW) return;
    int b = p / HWW, sp = p % HWW;
    const float* xp = x + (size_t)b * NPB + sp;
    float s = 0.f, sq = 0.f;
    #pragma unroll 4
    for (int c = 0; c < CC; c++) {
        float v = xp[(size_t)c * HWW];
        s += v; sq += v * v;
    }
    float mu = s * (1.0f / CC);
    float var = sq * (1.0f / CC) - mu * mu;
    g_mu[p] = mu;
    g_rs[p] = rsqrtf(var + 1e-5f);
}

// ============== bf16 mma.sync GEMM machinery (m16n8k16, double-buffered) ==============
#define A_BLK 132
#define B_BLK2 132
#define A_CH (16 * A_BLK)     // 2112 u32
#define B_CH (16 * B_BLK2)    // 2112 u32
#define BUF_U32 (A_CH + B_CH) // 4224
#define SMEM_DB (2 * BUF_U32 * 4)   // 33792 B

#define MMA_BF16(acc, a0, a1, a2, a3, b0, b1) \
    asm volatile( \
        "mma.sync.aligned.m16n8k16.row.col.f32.bf16.bf16.f32 " \
        "{%0,%1,%2,%3}, {%4,%5,%6,%7}, {%8,%9}, {%0,%1,%2,%3};" \
        : "+f"((acc)[0]), "+f"((acc)[1]), "+f"((acc)[2]), "+f"((acc)[3]) \
        : "r"(a0), "r"(a1), "r"(a2), "r"(a3), "r"(b0), "r"(b1))

// A fill from preformatted fragments: pure copy
__device__ __forceinline__ void fill_A_pre(uint32_t* Ab, const uint32_t* src, int tid) {
    #pragma unroll
    for (int u = 0; u < 2; u++) {
        int f = tid + u * 256;            // 0..511 uint4s
        int blk = f >> 5, lane = f & 31;
        uint4 v = ((const uint4*)src)[f];
        *(uint4*)(Ab + blk * A_BLK + lane * 4) = v;
    }
}

// A fill from fp32 matrix (final GEMM; arows guard)
__device__ __forceinline__ void fill_A_f32(uint32_t* Ab, const float* Amat,
                                           int kbase, int arows, int tid) {
    #pragma unroll
    for (int u = 0; u < 2; u++) {
        int unit = tid + u * 256;
        int koq  = unit & 3;
        int g    = (unit >> 2) & 7;
        int ks   = (unit >> 5) & 1;
        int msub = unit >> 6;
        int r0 = msub * 16 + g;
        int koff = koq * 4;
        int kk = kbase + ks * 16 + koff;
        float4 v0 = make_float4(0.f,0.f,0.f,0.f), v1 = v0;
        if (r0 < arows)     v0 = *(const float4*)&Amat[(size_t)r0 * CC + kk];
        if (r0 + 8 < arows) v1 = *(const float4*)&Amat[(size_t)(r0 + 8) * CC + kk];
        int lane0 = g * 4 + ((koq * 2) & 3);
        int regbase = (koff >= 8) ? 2 : 0;
        uint32_t* blk = Ab + (msub * 2 + ks) * A_BLK;
        *(uint2*)(blk + lane0 * 4 + regbase)       = make_uint2(bf2(v0.x, v0.y), bf2(v1.x, v1.y));
        *(uint2*)(blk + (lane0 + 1) * 4 + regbase) = make_uint2(bf2(v0.z, v0.w), bf2(v1.z, v1.w));
    }
}

// B stage 1: 4 coalesced LDG.128
__device__ __forceinline__ void load_B4(float4 v[4], const float* X,
                                        int kbase, int pix0, int tid) {
    int n4 = (tid & 31) * 4;
    int kp = (tid >> 5) & 3;
    int ks = tid >> 7;
    const float* base = X + (size_t)(kbase + ks * 16) * HWW + pix0 + n4;
    v[0] = *(const float4*)(base + (size_t)(2 * kp) * HWW);
    v[1] = *(const float4*)(base + (size_t)(2 * kp + 1) * HWW);
    v[2] = *(const float4*)(base + (size_t)(2 * kp + 8) * HWW);
    v[3] = *(const float4*)(base + (size_t)(2 * kp + 9) * HWW);
}

// B stage 2: (optional LN) + pack + STS, paired-nsub layout
template<bool LN>
__device__ __forceinline__ void store_B(uint32_t* Bb, const float4 v[4], int tid,
                                        const float4 mu4, const float4 r4,
                                        const float* __restrict__ lnw,
                                        const float* __restrict__ lnb, int kbase) {
    int n4 = (tid & 31) * 4;
    int kp = (tid >> 5) & 3;
    int ks = tid >> 7;
    float lw[4], lb[4];
    if (LN) {
        int kk = kbase + ks * 16;
        int kr0 = kk + 2 * kp, kr1 = kk + 2 * kp + 1, kr2 = kk + 2 * kp + 8, kr3 = kk + 2 * kp + 9;
        lw[0] = lnw[kr0]; lw[1] = lnw[kr1]; lw[2] = lnw[kr2]; lw[3] = lnw[kr3];
        lb[0] = lnb[kr0]; lb[1] = lnb[kr1]; lb[2] = lnb[kr2]; lb[3] = lnb[kr3];
    }
    const float* e0 = (const float*)&v[0];
    const float* e1 = (const float*)&v[1];
    const float* e2 = (const float*)&v[2];
    const float* e3 = (const float*)&v[3];
    const float* mup = (const float*)&mu4;
    const float* rp  = (const float*)&r4;
    #pragma unroll
    for (int q = 0; q < 4; q++) {
        float f0 = e0[q], f1 = e1[q], f2 = e2[q], f3 = e3[q];
        if (LN) {
            float sc = rp[q], mm = mup[q];
            f0 = (f0 - mm) * sc * lw[0] + lb[0];
            f1 = (f1 - mm) * sc * lw[1] + lb[1];
            f2 = (f2 - mm) * sc * lw[2] + lb[2];
            f3 = (f3 - mm) * sc * lw[3] + lb[3];
        }
        int n = n4 + q;
        int npair = n >> 4, sub = (n >> 3) & 1, lane = (n & 7) * 4 + kp;
        *(uint2*)(Bb + (npair * 2 + ks) * B_BLK2 + lane * 4 + sub * 2) =
            make_uint2(bf2(f0, f1), bf2(f2, f3));
    }
}

__device__ __forceinline__ void mma_chunk(float acc[4][4][4], const uint32_t* Ab,
                                          const uint32_t* Bb, int wm, int wnp, int lane) {
    #pragma unroll
    for (int ks = 0; ks < 2; ks++) {
        uint32_t ah[4][4], bh[4][2];
        #pragma unroll
        for (int i = 0; i < 4; i++) {
            uint4 t = *(const uint4*)(Ab + ((wm + i) * 2 + ks) * A_BLK + lane * 4);
            ah[i][0] = t.x; ah[i][1] = t.y; ah[i][2] = t.z; ah[i][3] = t.w;
        }
        #pragma unroll
        for (int jp = 0; jp < 2; jp++) {
            uint4 t = *(const uint4*)(Bb + ((wnp + jp) * 2 + ks) * B_BLK2 + lane * 4);
            bh[jp*2][0] = t.x; bh[jp*2][1] = t.y;
            bh[jp*2+1][0] = t.z; bh[jp*2+1][1] = t.w;
        }
        #pragma unroll
        for (int i = 0; i < 4; i++)
            #pragma unroll
            for (int j = 0; j < 4; j++)
                MMA_BF16(acc[i][j], ah[i][0], ah[i][1], ah[i][2], ah[i][3], bh[j][0], bh[j][1]);
    }
}

// Double-buffered mainloop. PRE: A preformatted (g_w3f chunk base) + LN on B.
template<bool PRE>
__device__ __forceinline__ void gemm_mainloop(float acc[4][4][4], uint32_t* usm,
                                              const void* Asrc, const float* X,
                                              int arows, int pix0, int tid,
                                              int wm, int wnp, int lane,
                                              const float* lnw, const float* lnb,
                                              const float* mup, const float* rsp) {
    float4 breg[4];
    float4 mu4 = make_float4(0.f,0.f,0.f,0.f), r4 = mu4;
    if (PRE) {
        int n4 = (tid & 31) * 4;
        mu4 = *(const float4*)&mup[pix0 + n4];
        r4  = *(const float4*)&rsp[pix0 + n4];
    }
    load_B4(breg, X, 0, pix0, tid);
    if (PRE) fill_A_pre(usm, (const uint32_t*)Asrc, tid);
    else     fill_A_f32(usm, (const float*)Asrc, 0, arows, tid);
    store_B<PRE>(usm + A_CH, breg, tid, mu4, r4, lnw, lnb, 0);
    __syncthreads();
    #pragma unroll 1
    for (int kc = 0; kc < 6; kc++) {
        uint32_t* cur = usm + (kc & 1) * BUF_U32;
        uint32_t* nxt = usm + ((kc + 1) & 1) * BUF_U32;
        if (kc < 5) load_B4(breg, X, (kc + 1) * 32, pix0, tid);
        mma_chunk(acc, cur, cur + A_CH, wm, wnp, lane);
        if (kc < 5) {
            if (PRE) fill_A_pre(nxt, (const uint32_t*)Asrc + (kc + 1) * 2048, tid);
            else     fill_A_f32(nxt, (const float*)Asrc, (kc + 1) * 32, arows, tid);
            store_B<PRE>(nxt + A_CH, breg, tid, mu4, r4, lnw, lnb, (kc + 1) * 32);
        }
        __syncthreads();
    }
}

// ---------------- QKV pointwise GEMM (LN fused into B path) ----------------
__global__ __launch_bounds__(256, 2) void gemm_qkv_mma_kernel(const float* __restrict__ x,
                                                              const float* __restrict__ lnw,
                                                              const float* __restrict__ lnb) {
    extern __shared__ uint32_t usm[];
    const int tid = threadIdx.x;
    const int wid = tid >> 5, lane = tid & 31;
    const int mb = blockIdx.x;              // m-block 0..4 (m-major: B tile L2-shared)
    const int pix0 = blockIdx.y * 128;
    const int b = blockIdx.z;
    const int m0 = mb * 128;
    const int wm = (wid & 1) * 4;
    const int wnp = (wid >> 1) * 2;

    float acc[4][4][4] = {};
    gemm_mainloop<true>(acc, usm, g_w3f + mb * 6 * 2048, x + (size_t)b * NPB,
                        128, pix0, tid, wm, wnp, lane,
                        lnw, lnb, g_mu + (size_t)b * HWW, g_rs + (size_t)b * HWW);

    int g = lane >> 2, t = lane & 3;
    #pragma unroll
    for (int i = 0; i < 4; i++) {
        #pragma unroll
        for (int half = 0; half < 2; half++) {
            int m = m0 + (wid & 1) * 64 + i * 16 + g + half * 8;
            if (m >= 576) continue;
            int slot = m / CC, o = m - slot * CC;
            float bias = g_b3[m];
            float* dst = g_tmp + (size_t)slot * NTOT + (size_t)b * NPB + (size_t)o * HWW;
            #pragma unroll
            for (int j = 0; j < 4; j++) {
                int pix = pix0 + (wid >> 1) * 32 + j * 8 + 2 * t;
                float2 v = make_float2(acc[i][j][half*2+0] + bias, acc[i][j][half*2+1] + bias);
                *(float2*)&dst[pix] = v;
            }
        }
    }
}

// ---------------- final GEMM: y = G[b] @ Vt + f_b + xn(recomputed) ----------------
__global__ __launch_bounds__(256, 2) void gemm_final_mma_kernel(const float* __restrict__ x,
                                                                const float* __restrict__ lnw,
                                                                const float* __restrict__ lnb,
                                                                const float* __restrict__ fb,
                                                                float* __restrict__ out) {
    extern __shared__ uint32_t usm[];
    const int tid = threadIdx.x;
    const int wid = tid >> 5, lane = tid & 31;
    const int m0 = blockIdx.x * 128;
    const int pix0 = blockIdx.y * 128;
    const int b = blockIdx.z;
    const int arows = (m0 == 0) ? 128 : (CC - 128);
    const int wm = (wid & 1) * 4;
    const int wnp = (wid >> 1) * 2;

    float acc[4][4][4] = {};
    gemm_mainloop<false>(acc, usm, g_Gm + ((size_t)b * 256 + m0) * CC,
                         g_qkv + 2 * (size_t)NTOT + (size_t)b * NPB,  // Vt
                         arows, pix0, tid, wm, wnp, lane,
                         nullptr, nullptr, nullptr, nullptr);

    int g = lane >> 2, t = lane & 3;
    const float* xb = x + (size_t)b * NPB;
    const float* mup = g_mu + (size_t)b * HWW;
    const float* rsp = g_rs + (size_t)b * HWW;
    // hoist per-j mu/r
    float2 m2a[4], r2a[4];
    #pragma unroll
    for (int j = 0; j < 4; j++) {
        int pix = pix0 + (wid >> 1) * 32 + j * 8 + 2 * t;
        m2a[j] = *(const float2*)&mup[pix];
        r2a[j] = *(const float2*)&rsp[pix];
    }
    #pragma unroll
    for (int i = 0; i < 4; i++) {
        #pragma unroll
        for (int half = 0; half < 2; half++) {
            int m = m0 + (wid & 1) * 64 + i * 16 + g + half * 8;
            if (m >= CC) continue;
            float bias = fb[m];
            float lwm = lnw[m], lbm = lnb[m];
            size_t base = (size_t)m * HWW;
            #pragma unroll
            for (int j = 0; j < 4; j++) {
                int pix = pix0 + (wid >> 1) * 32 + j * 8 + 2 * t;
                float2 xv = *(const float2*)&xb[base + pix];
                float xn0 = (xv.x - m2a[j].x) * r2a[j].x * lwm + lbm;
                float xn1 = (xv.y - m2a[j].y) * r2a[j].y * lwm + lbm;
                float2 v = make_float2(acc[i][j][half*2+0] + bias + xn0,
                                       acc[i][j][half*2+1] + bias + xn1);
                *(float2*)&out[(size_t)b * NPB + base + pix] = v;
            }
        }
    }
}

// ---------------- depthwise 3x3 SAME, 4 px/thread; slot2 writes spatially transposed ----------------
__global__ __launch_bounds__(256) void dw_kernel(const float* __restrict__ qw, const float* __restrict__ kw,
                                                 const float* __restrict__ vw, const float* __restrict__ qb,
                                                 const float* __restrict__ kb, const float* __restrict__ vb) {
    __shared__ float tsm[128][9];
    int slot = blockIdx.y;
    const float* wgt  = (slot == 0) ? qw : (slot == 1) ? kw : vw;
    const float* bias = (slot == 0) ? qb : (slot == 1) ? kb : vb;
    int tid = threadIdx.x;
    int idx = blockIdx.x * 256 + tid;
    const float* in = g_tmp + (size_t)slot * NTOT;
    int w4 = (idx & 31) * 4;
    int h = (idx >> 5) & (HH - 1);
    int cg = idx >> 12;                          // b*C + c
    int c = cg % CC;
    const float* ip = in + (size_t)cg * HWW;
    const float* wp = wgt + c * 9;
    float bv = bias[c];
    float a0 = bv, a1 = bv, a2 = bv, a3 = bv;
    #pragma unroll
    for (int dy = 0; dy < 3; dy++) {
        int hh = h + dy - 1;
        if (hh < 0 || hh >= HH) continue;
        const float* row = ip + hh * WW + w4;
        float4 m = *(const float4*)row;
        float lf = (w4 > 0)   ? row[-1] : 0.f;
        float rt = (w4 < 124) ? row[4]  : 0.f;
        float k0 = wp[dy*3], k1 = wp[dy*3+1], k2 = wp[dy*3+2];
        a0 += k0*lf  + k1*m.x + k2*m.y;
        a1 += k0*m.x + k1*m.y + k2*m.z;
        a2 += k0*m.y + k1*m.z + k2*m.w;
        a3 += k0*m.z + k1*m.w + k2*rt;
    }
    if (slot < 2) {
        float* out = g_qkv + (size_t)slot * NTOT;
        *(float4*)&out[(size_t)cg * HWW + h * WW + w4] = make_float4(a0, a1, a2, a3);
    } else {
        // stage and write transposed: Vt[w][h] = V[h][w]
        int hl = tid >> 5;
        tsm[w4 + 0][hl] = a0;
        tsm[w4 + 1][hl] = a1;
        tsm[w4 + 2][hl] = a2;
        tsm[w4 + 3][hl] = a3;
        __syncthreads();
        int wv = tid >> 1, half = tid & 1;
        int h0 = (blockIdx.x * 8) & (HH - 1);
        float4 o = make_float4(tsm[wv][half*4+0], tsm[wv][half*4+1],
                               tsm[wv][half*4+2], tsm[wv][half*4+3]);
        float* op = g_qkv + 2 * (size_t)NTOT + (size_t)cg * HWW;
        *(float4*)&op[wv * WW + h0 + half * 4] = o;
    }
}

// ---------------- per-(b,head) 48x48 Gram ----------------
#define GPITCH 129
__global__ __launch_bounds__(256) void gram_kernel() {
    __shared__ float Ks[SS * GPITCH];
    __shared__ float Qs[SS * GPITCH];
    int bh = blockIdx.x;
    int b = bh / NHEADS, hd = bh % NHEADS;
    int p0 = blockIdx.y * 128;
    const float* Qp = g_qkv + (size_t)b * NPB + (size_t)(hd * SS) * HWW + p0;
    const float* Kp = g_qkv + (size_t)NTOT + (size_t)b * NPB + (size_t)(hd * SS) * HWW + p0;
    int tid = threadIdx.x;
    for (int i = tid; i < SS * 128; i += 256) {
        int s = i >> 7, p = i & 127;
        Ks[s * GPITCH + p] = Kp[(size_t)s * HWW + p];
        Qs[s * GPITCH + p] = Qp[(size_t)s * HWW + p];
    }
    __syncthreads();
    int tx = tid & 15, ty = tid >> 4;
    int s0 = ty * 3, q0 = tx * 3;
    float acc[3][3] = {};
    for (int p = 0; p < 128; p++) {
        float kv0 = Ks[(s0 + 0) * GPITCH + p];
        float kv1 = Ks[(s0 + 1) * GPITCH + p];
        float kv2 = Ks[(s0 + 2) * GPITCH + p];
        float qv0 = Qs[(q0 + 0) * GPITCH + p];
        float qv1 = Qs[(q0 + 1) * GPITCH + p];
        float qv2 = Qs[(q0 + 2) * GPITCH + p];
        acc[0][0] += kv0 * qv0; acc[0][1] += kv0 * qv1; acc[0][2] += kv0 * qv2;
        acc[1][0] += kv1 * qv0; acc[1][1] += kv1 * qv1; acc[1][2] += kv1 * qv2;
        acc[2][0] += kv2 * qv0; acc[2][1] += kv2 * qv1; acc[2][2] += kv2 * qv2;
    }
    float* ap = g_att + (size_t)bh * SS * SS;
    #pragma unroll
    for (int i = 0; i < 3; i++)
        #pragma unroll
        for (int j = 0; j < 3; j++)
            atomicAdd(&ap[(s0 + i) * SS + q0 + j], acc[i][j]);
}

// ---------------- softmax over q ----------------
__global__ void softmax_kernel(const float* __restrict__ alpha) {
    int bh = blockIdx.x;
    int s = threadIdx.x;
    float inva = 1.0f / alpha[0];
    float* row = g_att + ((size_t)bh * SS + s) * SS;
    float mx = -1e30f;
    for (int q = 0; q < SS; q++) mx = fmaxf(mx, row[q] * inva);
    float sum = 0.f;
    for (int q = 0; q < SS; q++) sum += expf(row[q] * inva - mx);
    float rs = 1.0f / sum;
    for (int q = 0; q < SS; q++) row[q] = expf(row[q] * inva - mx) * rs;
}

// ---------------- build fused matrix g_Gm[b][o][cv] ----------------
__global__ void buildG_kernel(const float* __restrict__ fw) {
    int b = blockIdx.x, cv = blockIdx.y;
    int hd = cv / SS, sl = cv % SS;
    __shared__ float arow[SS];
    int o = threadIdx.x;
    if (o < SS) arow[o] = g_att[(((size_t)b * NHEADS + hd) * SS + sl) * SS + o];
    __syncthreads();
    const float* fp = fw + (size_t)o * CC + hd * SS;
    float acc = 0.f;
    #pragma unroll
    for (int q = 0; q < SS; q++) acc += fp[q] * arow[q];
    g_Gm[((size_t)b * 256 + o) * CC + cv] = acc;
}

// ---------------- launch ----------------
extern "C" void kernel_launch(void* const* d_in, const int* in_sizes, int n_in,
                              void* d_out, int out_size) {
    const float* x      = (const float*)d_in[0];
    const float* ln_w   = (const float*)d_in[1];
    const float* ln_b   = (const float*)d_in[2];
    const float* q_pw_w = (const float*)d_in[3];
    const float* q_pw_b = (const float*)d_in[4];
    const float* q_dw_w = (const float*)d_in[5];
    const float* q_dw_b = (const float*)d_in[6];
    const float* k_pw_w = (const float*)d_in[7];
    const float* k_pw_b = (const float*)d_in[8];
    const float* k_dw_w = (const float*)d_in[9];
    const float* k_dw_b = (const float*)d_in[10];
    const float* v_pw_w = (const float*)d_in[11];
    const float* v_pw_b = (const float*)d_in[12];
    const float* v_dw_w = (const float*)d_in[13];
    const float* v_dw_b = (const float*)d_in[14];
    const float* f_w    = (const float*)d_in[15];
    const float* f_b    = (const float*)d_in[16];
    const float* alpha  = (const float*)d_in[17];
    float* out = (float*)d_out;

    cudaFuncSetAttribute(gemm_qkv_mma_kernel,   cudaFuncAttributeMaxDynamicSharedMemorySize, SMEM_DB);
    cudaFuncSetAttribute(gemm_final_mma_kernel, cudaFuncAttributeMaxDynamicSharedMemorySize, SMEM_DB);

    prep_weights_kernel<<<(640 * CC + 255) / 256, 256>>>(q_pw_w, k_pw_w, v_pw_w,
                                                         q_pw_b, k_pw_b, v_pw_b);
    prep_frag_kernel<<<dim3(5, 6), 256>>>();
    zero_att_kernel<<<(BB * NHEADS * SS * SS + 255) / 256, 256>>>();
    ln_stats_kernel<<<(BB * HWW + 255) / 256, 256>>>(x);
    gemm_qkv_mma_kernel<<<dim3(5, HWW / 128, BB), 256, SMEM_DB>>>(x, ln_w, ln_b);
    dw_kernel<<<dim3(NTOT / 1024, 3), 256>>>(q_dw_w, k_dw_w, v_dw_w, q_dw_b, k_dw_b, v_dw_b);
    gram_kernel<<<dim3(BB * NHEADS, HWW / 128), 256>>>();
    softmax_kernel<<<BB * NHEADS, SS>>>(alpha);
    buildG_kernel<<<dim3(BB, CC), CC>>>(f_w);
    gemm_final_mma_kernel<<<dim3(2, HWW / 128, BB), 256, SMEM_DB>>>(x, ln_w, ln_b, f_b, out);
}